// round 11
// baseline (speedup 1.0000x reference)
#include <cuda_runtime.h>
#include <cstdint>

#define B_    8
#define L_    768
#define H_    16
#define DK_   64
#define D_    1024
#define BH_   128
#define M_    6144
#define SCALE 0.125f

// Scratch (device globals; allocation forbidden)
__device__ float g_Xr[3][M_ * D_];                     // tf32 inputs: q, k, v
__device__ float g_Wq[D_ * D_], g_Wk[D_ * D_], g_Wv[D_ * D_], g_Wo[D_ * D_];
__device__ float g_Qp[BH_ * L_ * DK_];                 // [bh][l][dk] tf32
__device__ float g_Kp[BH_ * L_ * DK_];                 // tf32
__device__ float g_Vt[BH_ * DK_ * L_];                 // V^T [bh][dk][l] tf32
__device__ float g_Ec[1535 * 64];                      // tf32 rel embedding
__device__ float g_S [(size_t)BH_ * L_ * L_];          // unnormalized probs (tf32)
__device__ float g_InvSum[BH_ * L_];                   // 1/rowsum
__device__ float g_O2[(size_t)M_ * D_];                // attn out, merged, tf32

__device__ __forceinline__ float to_tf32(float x) {
    float r;
    asm("cvt.rna.tf32.f32 %0, %1;" : "=f"(r) : "f"(x));
    return r;
}
__device__ __forceinline__ uint32_t smem_u32(const void* p) {
    uint32_t a;
    asm("{ .reg .u64 t; cvta.to.shared.u64 t, %1; cvt.u32.u64 %0, t; }"
        : "=r"(a) : "l"(p));
    return a;
}
__device__ __forceinline__ void mma_tf32(float* d, const uint32_t* a, const uint32_t* b) {
    asm volatile(
        "mma.sync.aligned.m16n8k8.row.col.f32.tf32.tf32.f32 "
        "{%0,%1,%2,%3}, {%4,%5,%6,%7}, {%8,%9}, {%0,%1,%2,%3};"
        : "+f"(d[0]), "+f"(d[1]), "+f"(d[2]), "+f"(d[3])
        : "r"(a[0]), "r"(a[1]), "r"(a[2]), "r"(a[3]), "r"(b[0]), "r"(b[1]));
}
#define CP_A16(dst, src) \
    asm volatile("cp.async.ca.shared.global [%0], [%1], 16;" :: "r"(dst), "l"(src) : "memory")
#define CP_A16Z(dst, src, sz) \
    asm volatile("cp.async.ca.shared.global [%0], [%1], 16, %2;" :: "r"(dst), "l"(src), "r"(sz) : "memory")
#define CP_COMMIT() asm volatile("cp.async.commit_group;" ::: "memory")
#define CP_WAIT2()  asm volatile("cp.async.wait_group 2;" ::: "memory")
#define CP_WAIT1()  asm volatile("cp.async.wait_group 1;" ::: "memory")
#define CP_WAIT0()  asm volatile("cp.async.wait_group 0;" ::: "memory")

// ---------------------------------------------------------------------------
// tf32 pre-round: z in [0,4] = {w_q, w_k, w_v, w_o, relE}
// ---------------------------------------------------------------------------
__global__ __launch_bounds__(256)
void conv_w(const float4* __restrict__ p0, const float4* __restrict__ p1,
            const float4* __restrict__ p2, const float4* __restrict__ p3,
            const float4* __restrict__ p4,
            float4* __restrict__ d0, float4* __restrict__ d1,
            float4* __restrict__ d2, float4* __restrict__ d3,
            float4* __restrict__ d4, int n4w, int n4e)
{
    const int z = blockIdx.z;
    const float4* in  = (z == 0) ? p0 : (z == 1) ? p1 : (z == 2) ? p2
                                      : (z == 3) ? p3 : p4;
    float4*       out = (z == 0) ? d0 : (z == 1) ? d1 : (z == 2) ? d2
                                      : (z == 3) ? d3 : d4;
    const int n4 = (z == 4) ? n4e : n4w;
    int i = blockIdx.x * 256 + threadIdx.x;
    if (i < n4) {
        float4 v = in[i];
        out[i] = make_float4(to_tf32(v.x), to_tf32(v.y), to_tf32(v.z), to_tf32(v.w));
    }
}
__global__ __launch_bounds__(256)
void conv_x(const float4* __restrict__ p0, const float4* __restrict__ p1,
            const float4* __restrict__ p2,
            float4* __restrict__ d0, float4* __restrict__ d1,
            float4* __restrict__ d2, int n4)
{
    const int z = blockIdx.z;
    const float4* in  = (z == 0) ? p0 : (z == 1) ? p1 : p2;
    float4*       out = (z == 0) ? d0 : (z == 1) ? d1 : d2;
    int i = blockIdx.x * 256 + threadIdx.x;
    if (i < n4) {
        float4 v = in[i];
        out[i] = make_float4(to_tf32(v.x), to_tf32(v.y), to_tf32(v.z), to_tf32(v.w));
    }
}

// ---------------------------------------------------------------------------
// QKV projection (R10-proven), fused over blockIdx.z (0=Q, 1=K, 2=V).
// C[128,128] tile, BK=32, 2-stage cp.async, stride-36 smem, warps 2m x 4n.
// ---------------------------------------------------------------------------
__global__ __launch_bounds__(256)
void proj_qkv(const float* __restrict__ bq, const float* __restrict__ bk,
              const float* __restrict__ bv, float* __restrict__ Qout,
              float* __restrict__ Kout)
{
    extern __shared__ float sm[];
    const uint32_t smb = smem_u32(sm);
    constexpr int STG = 2 * 128 * 36;

    const int tid = threadIdx.x, lane = tid & 31, wid = tid >> 5;
    const int g4 = lane >> 2, cq = lane & 3;
    const int wm = (wid & 1) * 64, wn = (wid >> 1) * 32;
    const int z = blockIdx.z;

    const float* Ag = g_Xr[z];
    const float* Bg = (z == 0) ? g_Wq : (z == 1) ? g_Wk : g_Wv;
    const float* bias = (z == 0) ? bq : (z == 1) ? bk : bv;

    const float* Arow = Ag + (size_t)(blockIdx.y * 128) * 1024;
    const float* Brow = Bg + (size_t)(blockIdx.x * 128) * 1024;

    auto loadAB = [&](int t, int s) {
        const uint32_t base = smb + (uint32_t)s * STG * 4;
        const int k0 = t * 32;
#pragma unroll
        for (int i = 0; i < 4; ++i) {
            int idx = tid + i * 256;
            int r = idx >> 3, seg = idx & 7;
            CP_A16(base + (uint32_t)(r * 36 + seg * 4) * 4,
                   Arow + (size_t)r * 1024 + k0 + seg * 4);
        }
#pragma unroll
        for (int i = 0; i < 4; ++i) {
            int idx = tid + i * 256;
            int r = idx >> 3, seg = idx & 7;
            CP_A16(base + (uint32_t)(128 * 36 + r * 36 + seg * 4) * 4,
                   Brow + (size_t)r * 1024 + k0 + seg * 4);
        }
    };

    float acc[4][4][4] = {};

    loadAB(0, 0); CP_COMMIT();

    for (int t = 0; t < 32; ++t) {
        if (t + 1 < 32) { loadAB(t + 1, (t + 1) & 1); CP_COMMIT(); }
        if (t + 1 < 32) { CP_WAIT1(); } else { CP_WAIT0(); }
        __syncthreads();

        const float* As = sm + (t & 1) * STG;
        const float* Bs = As + 128 * 36;
#pragma unroll
        for (int ks = 0; ks < 4; ++ks) {
            uint32_t afr[4][4], bfr[4][2];
#pragma unroll
            for (int m = 0; m < 4; ++m) {
                const float* p = As + (wm + m * 16 + g4) * 36 + ks * 8 + cq;
                afr[m][0] = __float_as_uint(p[0]);
                afr[m][1] = __float_as_uint(p[8 * 36]);
                afr[m][2] = __float_as_uint(p[4]);
                afr[m][3] = __float_as_uint(p[8 * 36 + 4]);
            }
#pragma unroll
            for (int n = 0; n < 4; ++n) {
                const float* p = Bs + (wn + n * 8 + g4) * 36 + ks * 8 + cq;
                bfr[n][0] = __float_as_uint(p[0]);
                bfr[n][1] = __float_as_uint(p[4]);
            }
#pragma unroll
            for (int m = 0; m < 4; ++m)
#pragma unroll
                for (int n = 0; n < 4; ++n)
                    mma_tf32(acc[m][n], afr[m], bfr[n]);
        }
        __syncthreads();
    }

    float* OUT = (z == 0) ? Qout : Kout;
#pragma unroll
    for (int m = 0; m < 4; ++m) {
#pragma unroll
        for (int n = 0; n < 4; ++n) {
            const int col = wn + n * 8 + cq * 2;
#pragma unroll
            for (int h2 = 0; h2 < 2; ++h2) {
                const int row = wm + m * 16 + g4 + h2 * 8;
                const float c0 = acc[m][n][h2 * 2 + 0];
                const float c1 = acc[m][n][h2 * 2 + 1];
                const int mg = blockIdx.y * 128 + row;
                const int ng = blockIdx.x * 128 + col;
                const int bb = mg / 768, l = mg - bb * 768;
                const int hh = ng >> 6, dd = ng & 63;
                if (z < 2) {
                    float* dst = OUT + (((size_t)(bb * 16 + hh) * 768) + l) * 64 + dd;
                    dst[0] = to_tf32(c0 + bias[ng]);
                    dst[1] = to_tf32(c1 + bias[ng + 1]);
                } else {
                    g_Vt[((size_t)(bb * 16 + hh) * 64 + dd    ) * 768 + l] = to_tf32(c0 + bias[ng]);
                    g_Vt[((size_t)(bb * 16 + hh) * 64 + dd + 1) * 768 + l] = to_tf32(c1 + bias[ng + 1]);
                }
            }
        }
    }
}

// ---------------------------------------------------------------------------
// Output projection (R10-proven): 2-stage, plain fp32 OUT.
// ---------------------------------------------------------------------------
__global__ __launch_bounds__(256)
void proj_out(const float* __restrict__ bias, float* __restrict__ OUT)
{
    extern __shared__ float sm[];
    const uint32_t smb = smem_u32(sm);
    constexpr int STG = 2 * 128 * 36;

    const int tid = threadIdx.x, lane = tid & 31, wid = tid >> 5;
    const int g4 = lane >> 2, cq = lane & 3;
    const int wm = (wid & 1) * 64, wn = (wid >> 1) * 32;

    const float* Arow = g_O2 + (size_t)(blockIdx.y * 128) * 1024;
    const float* Brow = g_Wo + (size_t)(blockIdx.x * 128) * 1024;

    auto loadAB = [&](int t, int s) {
        const uint32_t base = smb + (uint32_t)s * STG * 4;
        const int k0 = t * 32;
#pragma unroll
        for (int i = 0; i < 4; ++i) {
            int idx = tid + i * 256;
            int r = idx >> 3, seg = idx & 7;
            CP_A16(base + (uint32_t)(r * 36 + seg * 4) * 4,
                   Arow + (size_t)r * 1024 + k0 + seg * 4);
        }
#pragma unroll
        for (int i = 0; i < 4; ++i) {
            int idx = tid + i * 256;
            int r = idx >> 3, seg = idx & 7;
            CP_A16(base + (uint32_t)(128 * 36 + r * 36 + seg * 4) * 4,
                   Brow + (size_t)r * 1024 + k0 + seg * 4);
        }
    };

    float acc[4][4][4] = {};

    loadAB(0, 0); CP_COMMIT();

    for (int t = 0; t < 32; ++t) {
        if (t + 1 < 32) { loadAB(t + 1, (t + 1) & 1); CP_COMMIT(); }
        if (t + 1 < 32) { CP_WAIT1(); } else { CP_WAIT0(); }
        __syncthreads();

        const float* As = sm + (t & 1) * STG;
        const float* Bs = As + 128 * 36;
#pragma unroll
        for (int ks = 0; ks < 4; ++ks) {
            uint32_t afr[4][4], bfr[4][2];
#pragma unroll
            for (int m = 0; m < 4; ++m) {
                const float* p = As + (wm + m * 16 + g4) * 36 + ks * 8 + cq;
                afr[m][0] = __float_as_uint(p[0]);
                afr[m][1] = __float_as_uint(p[8 * 36]);
                afr[m][2] = __float_as_uint(p[4]);
                afr[m][3] = __float_as_uint(p[8 * 36 + 4]);
            }
#pragma unroll
            for (int n = 0; n < 4; ++n) {
                const float* p = Bs + (wn + n * 8 + g4) * 36 + ks * 8 + cq;
                bfr[n][0] = __float_as_uint(p[0]);
                bfr[n][1] = __float_as_uint(p[4]);
            }
#pragma unroll
            for (int m = 0; m < 4; ++m)
#pragma unroll
                for (int n = 0; n < 4; ++n)
                    mma_tf32(acc[m][n], afr[m], bfr[n]);
        }
        __syncthreads();
    }

#pragma unroll
    for (int m = 0; m < 4; ++m) {
#pragma unroll
        for (int n = 0; n < 4; ++n) {
            const int col = wn + n * 8 + cq * 2;
#pragma unroll
            for (int h2 = 0; h2 < 2; ++h2) {
                const int row = wm + m * 16 + g4 + h2 * 8;
                const int mg = blockIdx.y * 128 + row;
                const int ng = blockIdx.x * 128 + col;
                float* dst = OUT + (size_t)mg * 1024 + ng;
                dst[0] = acc[m][n][h2 * 2 + 0] + bias[ng];
                dst[1] = acc[m][n][h2 * 2 + 1] + bias[ng + 1];
            }
        }
    }
}

// ---------------------------------------------------------------------------
// Fused scores + rel + exp + rowsum (R7-proven). One CTA per (qt, bh).
// ---------------------------------------------------------------------------
__global__ __launch_bounds__(256)
void scores_fused()
{
    extern __shared__ float sm[];
    float* Bbuf = sm;                       // [2][128*68]
    float* Wbuf = sm + 2 * 128 * 68;        // [2][128*132]
    const uint32_t bb_a = smem_u32(Bbuf);
    const uint32_t wq_a = smem_u32(Wbuf);
    __shared__ float ssum[128];

    const int tid  = threadIdx.x;
    const int lane = tid & 31, wid = tid >> 5;
    const int g4 = lane >> 2, cq = lane & 3;
    const int wm = (wid & 3) * 32, wn = (wid >> 2) * 64;
    const int qt = blockIdx.x, bh = blockIdx.y;

    if (tid < 128) ssum[tid] = 0.f;

    const float* Qg = g_Qp + ((size_t)bh * 768 + qt * 128) * 64;
    const float* Kg = g_Kp + (size_t)bh * 768 * 64;
    const int base0 = 640 - qt * 128;

#pragma unroll
    for (int i = 0; i < 8; ++i) {
        int idx = tid + i * 256;
        int r = idx >> 4, seg = idx & 15;
        CP_A16(wq_a + (uint32_t)(r * 68 + seg * 4) * 4, Qg + r * 64 + seg * 4);
    }
    CP_COMMIT();

    auto loadB = [&](int i) {
        const uint32_t base = bb_a + (uint32_t)(i & 1) * (128 * 68 * 4);
        const bool content = (i >= 2) && ((i & 1) == 0);
        if (content) {
            const int xt = (i - 2) >> 1;
            const float* s0 = Kg + (size_t)xt * 128 * 64;
#pragma unroll
            for (int k = 0; k < 8; ++k) {
                int idx = tid + k * 256;
                int r = idx >> 4, seg = idx & 15;
                CP_A16(base + (uint32_t)(r * 68 + seg * 4) * 4, s0 + r * 64 + seg * 4);
            }
        } else {
            const int w = (i < 2) ? i : ((i + 1) >> 1);
            const int jb = base0 + w * 128;
#pragma unroll
            for (int k = 0; k < 8; ++k) {
                int idx = tid + k * 256;
                int r = idx >> 4, seg = idx & 15;
                int j = jb + r;
                int jc = (j > 1534) ? 1534 : j;
                unsigned sz = (j <= 1534) ? 16u : 0u;
                CP_A16Z(base + (uint32_t)(r * 68 + seg * 4) * 4,
                        g_Ec + (size_t)jc * 64 + seg * 4, sz);
            }
        }
    };

    loadB(0); CP_COMMIT();
    loadB(1); CP_COMMIT();

    CP_WAIT2();
    __syncthreads();

    uint32_t afr[8][2][4];
#pragma unroll
    for (int ks = 0; ks < 8; ++ks)
#pragma unroll
        for (int mt = 0; mt < 2; ++mt) {
            const float* q = Wbuf + (wm + mt * 16 + g4) * 68 + ks * 8 + cq;
            afr[ks][mt][0] = __float_as_uint(q[0]);
            afr[ks][mt][1] = __float_as_uint(q[8 * 68]);
            afr[ks][mt][2] = __float_as_uint(q[4]);
            afr[ks][mt][3] = __float_as_uint(q[8 * 68 + 4]);
        }
    __syncthreads();

    CP_WAIT1();
    __syncthreads();

    float rsum[4] = {0.f, 0.f, 0.f, 0.f};

#pragma unroll 1
    for (int i = 0; i < 13; ++i) {
        const float* Bsb = Bbuf + (i & 1) * (128 * 68);
        float acc[2][8][4] = {};

#pragma unroll
        for (int ks = 0; ks < 8; ++ks) {
            uint32_t bfr[8][2];
#pragma unroll
            for (int nt = 0; nt < 8; ++nt) {
                const float* b = Bsb + (wn + nt * 8 + g4) * 68 + ks * 8 + cq;
                bfr[nt][0] = __float_as_uint(b[0]);
                bfr[nt][1] = __float_as_uint(b[4]);
            }
#pragma unroll
            for (int mt = 0; mt < 2; ++mt)
#pragma unroll
                for (int nt = 0; nt < 8; ++nt)
                    mma_tf32(acc[mt][nt], afr[ks][mt], bfr[nt]);
        }

        const bool content = (i >= 2) && ((i & 1) == 0);
        if (!content) {
            const int w = (i < 2) ? i : ((i + 1) >> 1);
            float* Wd = Wbuf + (w & 1) * (128 * 132);
#pragma unroll
            for (int mt = 0; mt < 2; ++mt)
#pragma unroll
                for (int h2 = 0; h2 < 2; ++h2) {
                    const int row = wm + mt * 16 + g4 + h2 * 8;
#pragma unroll
                    for (int nt = 0; nt < 8; ++nt) {
                        const int col = wn + nt * 8 + 2 * cq;
                        Wd[row * 132 + col    ] = acc[mt][nt][h2 * 2 + 0];
                        Wd[row * 132 + col + 1] = acc[mt][nt][h2 * 2 + 1];
                    }
                }
        } else {
            const int xt = (i - 2) >> 1;
            const float* W0 = Wbuf + (xt & 1) * (128 * 132);
            const float* W1 = Wbuf + ((xt + 1) & 1) * (128 * 132);
            float* Sd = g_S + ((size_t)bh * 768 + qt * 128) * 768 + xt * 128;
#pragma unroll
            for (int mt = 0; mt < 2; ++mt)
#pragma unroll
                for (int h2 = 0; h2 < 2; ++h2) {
                    const int row = wm + mt * 16 + g4 + h2 * 8;
                    float rs = 0.f;
#pragma unroll
                    for (int nt = 0; nt < 8; ++nt) {
                        const int col = wn + nt * 8 + 2 * cq;
                        const int c0 = col - row + 127;
                        const int c1 = c0 + 1;
                        const float r0 = (c0 < 128) ? W0[row * 132 + c0]
                                                    : W1[row * 132 + c0 - 128];
                        const float r1 = (c1 < 128) ? W0[row * 132 + c1]
                                                    : W1[row * 132 + c1 - 128];
                        const float p0 = __expf(SCALE * (acc[mt][nt][h2 * 2 + 0] + r0));
                        const float p1 = __expf(SCALE * (acc[mt][nt][h2 * 2 + 1] + r1));
                        rs += p0 + p1;
                        *(float2*)&Sd[(size_t)row * 768 + col] =
                            make_float2(to_tf32(p0), to_tf32(p1));
                    }
                    rsum[mt * 2 + h2] += rs;
                }
        }

        __syncthreads();
        if (i + 2 < 13) { loadB(i + 2); CP_COMMIT(); }
        if (i + 1 < 13) {
            if (i + 2 < 13) { CP_WAIT1(); } else { CP_WAIT0(); }
            __syncthreads();
        }
    }

#pragma unroll
    for (int k = 0; k < 4; ++k) {
        rsum[k] += __shfl_xor_sync(0xffffffffu, rsum[k], 1);
        rsum[k] += __shfl_xor_sync(0xffffffffu, rsum[k], 2);
    }
    __syncthreads();
    if (cq == 0) {
#pragma unroll
        for (int k = 0; k < 4; ++k) {
            const int row = wm + (k >> 1) * 16 + g4 + (k & 1) * 8;
            atomicAdd(&ssum[row], rsum[k]);
        }
    }
    __syncthreads();
    if (tid < 128)
        g_InvSum[bh * 768 + qt * 128 + tid] = 1.0f / ssum[tid];
}

// ---------------------------------------------------------------------------
// AV GEMM (new): C[128,64] = P[128,768] @ Vt[64,768]^T per (qt,bh).
// 128 threads = 4 warps (2m x 2n), warp tile 64x32 (LDS:MMA = 1.5).
// BK=32, 2-stage cp.async, 55.3 KB smem -> 4 CTAs/SM.
// ---------------------------------------------------------------------------
__global__ __launch_bounds__(128)
void av_mma()
{
    extern __shared__ float sm[];
    constexpr int STG = (128 + 64) * 36;     // floats per stage
    const uint32_t smb = smem_u32(sm);

    const int tid = threadIdx.x, lane = tid & 31, wid = tid >> 5;
    const int g4 = lane >> 2, cq = lane & 3;
    const int wm = (wid & 1) * 64, wn = (wid >> 1) * 32;
    const int qt = blockIdx.x, bh = blockIdx.y;

    const float* P = g_S  + ((size_t)bh * 768 + qt * 128) * 768;
    const float* V = g_Vt + (size_t)bh * 64 * 768;

    auto load = [&](int t, int s) {
        const uint32_t base = smb + (uint32_t)s * STG * 4;
        const int k0 = t * 32;
#pragma unroll
        for (int i = 0; i < 8; ++i) {
            int idx = tid + i * 128;
            int r = idx >> 3, seg = idx & 7;
            CP_A16(base + (uint32_t)(r * 36 + seg * 4) * 4,
                   P + (size_t)r * 768 + k0 + seg * 4);
        }
#pragma unroll
        for (int i = 0; i < 4; ++i) {
            int idx = tid + i * 128;
            int r = idx >> 3, seg = idx & 7;
            CP_A16(base + (uint32_t)(128 * 36 + r * 36 + seg * 4) * 4,
                   V + (size_t)r * 768 + k0 + seg * 4);
        }
    };

    float acc[4][4][4] = {};

    load(0, 0); CP_COMMIT();

    for (int t = 0; t < 24; ++t) {
        if (t + 1 < 24) { load(t + 1, (t + 1) & 1); CP_COMMIT(); }
        if (t + 1 < 24) { CP_WAIT1(); } else { CP_WAIT0(); }
        __syncthreads();

        const float* As = sm + (t & 1) * STG;
        const float* Bs = As + 128 * 36;
#pragma unroll
        for (int ks = 0; ks < 4; ++ks) {
            uint32_t afr[4][4], bfr[4][2];
#pragma unroll
            for (int m = 0; m < 4; ++m) {
                const float* p = As + (wm + m * 16 + g4) * 36 + ks * 8 + cq;
                afr[m][0] = __float_as_uint(p[0]);
                afr[m][1] = __float_as_uint(p[8 * 36]);
                afr[m][2] = __float_as_uint(p[4]);
                afr[m][3] = __float_as_uint(p[8 * 36 + 4]);
            }
#pragma unroll
            for (int n = 0; n < 4; ++n) {
                const float* p = Bs + (wn + n * 8 + g4) * 36 + ks * 8 + cq;
                bfr[n][0] = __float_as_uint(p[0]);
                bfr[n][1] = __float_as_uint(p[4]);
            }
#pragma unroll
            for (int m = 0; m < 4; ++m)
#pragma unroll
                for (int n = 0; n < 4; ++n)
                    mma_tf32(acc[m][n], afr[m], bfr[n]);
        }
        __syncthreads();
    }

    const int b = bh >> 4, h = bh & 15;
#pragma unroll
    for (int m = 0; m < 4; ++m)
#pragma unroll
        for (int h2 = 0; h2 < 2; ++h2) {
            const int row = wm + m * 16 + g4 + h2 * 8;
            const float inv = g_InvSum[bh * 768 + qt * 128 + row];
#pragma unroll
            for (int n = 0; n < 4; ++n) {
                const int col = wn + n * 8 + 2 * cq;
                *(float2*)&g_O2[((size_t)(b * 768) + qt * 128 + row) * 1024
                                + h * 64 + col] =
                    make_float2(to_tf32(acc[m][n][h2 * 2 + 0] * inv),
                                to_tf32(acc[m][n][h2 * 2 + 1] * inv));
            }
        }
}

// ---------------------------------------------------------------------------
extern "C" void kernel_launch(void* const* d_in, const int* in_sizes, int n_in,
                              void* d_out, int out_size)
{
    const float* query = (const float*)d_in[0];
    const float* key   = (const float*)d_in[1];
    const float* value = (const float*)d_in[2];
    const float* w_q   = (const float*)d_in[3];
    const float* b_q   = (const float*)d_in[4];
    const float* w_k   = (const float*)d_in[5];
    const float* b_k   = (const float*)d_in[6];
    const float* w_v   = (const float*)d_in[7];
    const float* b_v   = (const float*)d_in[8];
    const float* w_o   = (const float*)d_in[9];
    const float* b_o   = (const float*)d_in[10];
    const float* relE  = (const float*)d_in[11];
    float* out = (float*)d_out;

    float *xr, *wq, *wk, *wv, *wo, *qp, *kp, *ec;
    cudaGetSymbolAddress((void**)&xr, g_Xr);
    cudaGetSymbolAddress((void**)&wq, g_Wq);
    cudaGetSymbolAddress((void**)&wk, g_Wk);
    cudaGetSymbolAddress((void**)&wv, g_Wv);
    cudaGetSymbolAddress((void**)&wo, g_Wo);
    cudaGetSymbolAddress((void**)&qp, g_Qp);
    cudaGetSymbolAddress((void**)&kp, g_Kp);
    cudaGetSymbolAddress((void**)&ec, g_Ec);

    const int SMEMP   = 2 * 2 * 128 * 36 * 4;                    // 73728
    const int SC_SMEM = (2 * 128 * 68 + 2 * 128 * 132) * 4;      // 204800
    const int AV_SMEM = 2 * (128 + 64) * 36 * 4;                 // 55296
    cudaFuncSetAttribute(proj_qkv, cudaFuncAttributeMaxDynamicSharedMemorySize, SMEMP);
    cudaFuncSetAttribute(proj_out, cudaFuncAttributeMaxDynamicSharedMemorySize, SMEMP);
    cudaFuncSetAttribute(scores_fused, cudaFuncAttributeMaxDynamicSharedMemorySize, SC_SMEM);
    cudaFuncSetAttribute(av_mma,       cudaFuncAttributeMaxDynamicSharedMemorySize, AV_SMEM);

    const int NW4 = 1024 * 1024 / 4;
    const int NE4 = 1535 * 64 / 4;
    const int NX4 = M_ * D_ / 4;

    // weights + rel embedding (5-way z-batched)
    conv_w<<<dim3((NW4 + 255) / 256, 1, 5), 256>>>(
        (const float4*)w_q, (const float4*)w_k, (const float4*)w_v,
        (const float4*)w_o, (const float4*)relE,
        (float4*)wq, (float4*)wk, (float4*)wv, (float4*)wo, (float4*)ec,
        NW4, NE4);

    // inputs (3-way z-batched into g_Xr[0..2])
    conv_x<<<dim3((NX4 + 255) / 256, 1, 3), 256>>>(
        (const float4*)query, (const float4*)key, (const float4*)value,
        (float4*)(xr), (float4*)(xr + M_ * D_), (float4*)(xr + 2 * M_ * D_), NX4);

    // fused QKV projection: one launch, 3 full projections
    proj_qkv<<<dim3(8, 48, 3), 256, SMEMP>>>(b_q, b_k, b_v, qp, kp);

    scores_fused<<<dim3(6, 128), 256, SC_SMEM>>>();
    av_mma<<<dim3(6, 128), 128, AV_SMEM>>>();

    proj_out<<<dim3(8, 48), 256, SMEMP>>>(b_o, out);
}

// round 12
// speedup vs baseline: 1.0074x; 1.0074x over previous
#include <cuda_runtime.h>
#include <cstdint>

#define B_    8
#define L_    768
#define H_    16
#define DK_   64
#define D_    1024
#define BH_   128
#define M_    6144
#define SCALE 0.125f

// Scratch (device globals; allocation forbidden)
__device__ float g_Xr[3][M_ * D_];                     // tf32 inputs, k-permuted
__device__ float g_Wq[D_ * D_], g_Wk[D_ * D_], g_Wv[D_ * D_], g_Wo[D_ * D_];
__device__ float g_Qp[BH_ * L_ * DK_];                 // [bh][l][dk] tf32
__device__ float g_Kp[BH_ * L_ * DK_];                 // tf32
__device__ float g_Vt[BH_ * DK_ * L_];                 // V^T [bh][dk][l] tf32
__device__ float g_Ec[1535 * 64];                      // tf32 rel embedding (NOT permuted)
__device__ float g_S [(size_t)BH_ * L_ * L_];          // unnormalized probs (tf32)
__device__ float g_InvSum[BH_ * L_];                   // 1/rowsum
__device__ float g_O2[(size_t)M_ * D_];                // attn out, merged, tf32, D-permuted

__device__ __forceinline__ float to_tf32(float x) {
    float r;
    asm("cvt.rna.tf32.f32 %0, %1;" : "=f"(r) : "f"(x));
    return r;
}
__device__ __forceinline__ uint32_t smem_u32(const void* p) {
    uint32_t a;
    asm("{ .reg .u64 t; cvta.to.shared.u64 t, %1; cvt.u32.u64 %0, t; }"
        : "=r"(a) : "l"(p));
    return a;
}
__device__ __forceinline__ void mma_tf32(float* d, const uint32_t* a, const uint32_t* b) {
    asm volatile(
        "mma.sync.aligned.m16n8k8.row.col.f32.tf32.tf32.f32 "
        "{%0,%1,%2,%3}, {%4,%5,%6,%7}, {%8,%9}, {%0,%1,%2,%3};"
        : "+f"(d[0]), "+f"(d[1]), "+f"(d[2]), "+f"(d[3])
        : "r"(a[0]), "r"(a[1]), "r"(a[2]), "r"(a[3]), "r"(b[0]), "r"(b[1]));
}
#define CP_A16(dst, src) \
    asm volatile("cp.async.ca.shared.global [%0], [%1], 16;" :: "r"(dst), "l"(src) : "memory")
#define CP_A16Z(dst, src, sz) \
    asm volatile("cp.async.ca.shared.global [%0], [%1], 16, %2;" :: "r"(dst), "l"(src), "r"(sz) : "memory")
#define CP_COMMIT() asm volatile("cp.async.commit_group;" ::: "memory")
#define CP_WAIT2()  asm volatile("cp.async.wait_group 2;" ::: "memory")
#define CP_WAIT1()  asm volatile("cp.async.wait_group 1;" ::: "memory")
#define CP_WAIT0()  asm volatile("cp.async.wait_group 0;" ::: "memory")

// ---------------------------------------------------------------------------
// tf32 pre-round + within-8 k-permutation p(j) = (j&3)*2 + (j>>2).
// For float4 at index i: elements e=4i..4i+3; block = i>>1; offset = i&1;
// out[block*8 + offset + 2*c] = v[c].
// ---------------------------------------------------------------------------
__global__ __launch_bounds__(256)
void conv_w(const float4* __restrict__ p0, const float4* __restrict__ p1,
            const float4* __restrict__ p2, const float4* __restrict__ p3,
            const float4* __restrict__ p4,
            float* __restrict__ d0, float* __restrict__ d1,
            float* __restrict__ d2, float* __restrict__ d3,
            float4* __restrict__ d4, int n4w, int n4e)
{
    const int z = blockIdx.z;
    int i = blockIdx.x * 256 + threadIdx.x;
    if (z == 4) {
        if (i < n4e) {
            float4 v = p4[i];
            d4[i] = make_float4(to_tf32(v.x), to_tf32(v.y), to_tf32(v.z), to_tf32(v.w));
        }
        return;
    }
    const float4* in = (z == 0) ? p0 : (z == 1) ? p1 : (z == 2) ? p2 : p3;
    float*       out = (z == 0) ? d0 : (z == 1) ? d1 : (z == 2) ? d2 : d3;
    if (i < n4w) {
        float4 v = in[i];
        const int base = (i >> 1) * 8 + (i & 1);
        out[base + 0] = to_tf32(v.x);
        out[base + 2] = to_tf32(v.y);
        out[base + 4] = to_tf32(v.z);
        out[base + 6] = to_tf32(v.w);
    }
}
__global__ __launch_bounds__(256)
void conv_x(const float4* __restrict__ p0, const float4* __restrict__ p1,
            const float4* __restrict__ p2,
            float* __restrict__ d0, float* __restrict__ d1,
            float* __restrict__ d2, int n4)
{
    const int z = blockIdx.z;
    const float4* in = (z == 0) ? p0 : (z == 1) ? p1 : p2;
    float*       out = (z == 0) ? d0 : (z == 1) ? d1 : d2;
    int i = blockIdx.x * 256 + threadIdx.x;
    if (i < n4) {
        float4 v = in[i];
        const int base = (i >> 1) * 8 + (i & 1);
        out[base + 0] = to_tf32(v.x);
        out[base + 2] = to_tf32(v.y);
        out[base + 4] = to_tf32(v.z);
        out[base + 6] = to_tf32(v.w);
    }
}

// ---------------------------------------------------------------------------
// QKV projection, k-permuted operands, LDS.64 fragments, stride-40 smem.
// C[128,128] tile, BK=32, 2-stage cp.async; fused over blockIdx.z (Q/K/V).
// ---------------------------------------------------------------------------
__global__ __launch_bounds__(256)
void proj_qkv(const float* __restrict__ bq, const float* __restrict__ bk,
              const float* __restrict__ bv, float* __restrict__ Qout,
              float* __restrict__ Kout)
{
    extern __shared__ float sm[];
    const uint32_t smb = smem_u32(sm);
    constexpr int STG = 2 * 128 * 40;

    const int tid = threadIdx.x, lane = tid & 31, wid = tid >> 5;
    const int g4 = lane >> 2, cq = lane & 3;
    const int wm = (wid & 1) * 64, wn = (wid >> 1) * 32;
    const int z = blockIdx.z;

    const float* Ag = g_Xr[z];
    const float* Bg = (z == 0) ? g_Wq : (z == 1) ? g_Wk : g_Wv;
    const float* bias = (z == 0) ? bq : (z == 1) ? bk : bv;

    const float* Arow = Ag + (size_t)(blockIdx.y * 128) * 1024;
    const float* Brow = Bg + (size_t)(blockIdx.x * 128) * 1024;

    auto loadAB = [&](int t, int s) {
        const uint32_t base = smb + (uint32_t)s * STG * 4;
        const int k0 = t * 32;
#pragma unroll
        for (int i = 0; i < 4; ++i) {
            int idx = tid + i * 256;
            int r = idx >> 3, seg = idx & 7;
            CP_A16(base + (uint32_t)(r * 40 + seg * 4) * 4,
                   Arow + (size_t)r * 1024 + k0 + seg * 4);
        }
#pragma unroll
        for (int i = 0; i < 4; ++i) {
            int idx = tid + i * 256;
            int r = idx >> 3, seg = idx & 7;
            CP_A16(base + (uint32_t)(128 * 40 + r * 40 + seg * 4) * 4,
                   Brow + (size_t)r * 1024 + k0 + seg * 4);
        }
    };

    float acc[4][4][4] = {};

    loadAB(0, 0); CP_COMMIT();

    for (int t = 0; t < 32; ++t) {
        if (t + 1 < 32) { loadAB(t + 1, (t + 1) & 1); CP_COMMIT(); }
        if (t + 1 < 32) { CP_WAIT1(); } else { CP_WAIT0(); }
        __syncthreads();

        const float* As = sm + (t & 1) * STG;
        const float* Bs = As + 128 * 40;
#pragma unroll
        for (int ks = 0; ks < 4; ++ks) {
            uint32_t afr[4][4], bfr[4][2];
#pragma unroll
            for (int m = 0; m < 4; ++m) {
                const float* p = As + (wm + m * 16 + g4) * 40 + ks * 8 + 2 * cq;
                float2 lo = *(const float2*)p;
                float2 hi = *(const float2*)(p + 8 * 40);
                afr[m][0] = __float_as_uint(lo.x);
                afr[m][1] = __float_as_uint(hi.x);
                afr[m][2] = __float_as_uint(lo.y);
                afr[m][3] = __float_as_uint(hi.y);
            }
#pragma unroll
            for (int n = 0; n < 4; ++n) {
                const float* p = Bs + (wn + n * 8 + g4) * 40 + ks * 8 + 2 * cq;
                float2 b = *(const float2*)p;
                bfr[n][0] = __float_as_uint(b.x);
                bfr[n][1] = __float_as_uint(b.y);
            }
#pragma unroll
            for (int m = 0; m < 4; ++m)
#pragma unroll
                for (int n = 0; n < 4; ++n)
                    mma_tf32(acc[m][n], afr[m], bfr[n]);
        }
        __syncthreads();
    }

    float* OUT = (z == 0) ? Qout : Kout;
#pragma unroll
    for (int m = 0; m < 4; ++m) {
#pragma unroll
        for (int n = 0; n < 4; ++n) {
            const int col = wn + n * 8 + cq * 2;
#pragma unroll
            for (int h2 = 0; h2 < 2; ++h2) {
                const int row = wm + m * 16 + g4 + h2 * 8;
                const float c0 = acc[m][n][h2 * 2 + 0];
                const float c1 = acc[m][n][h2 * 2 + 1];
                const int mg = blockIdx.y * 128 + row;
                const int ng = blockIdx.x * 128 + col;
                const int bb = mg / 768, l = mg - bb * 768;
                const int hh = ng >> 6, dd = ng & 63;
                if (z < 2) {
                    float* dst = OUT + (((size_t)(bb * 16 + hh) * 768) + l) * 64 + dd;
                    dst[0] = to_tf32(c0 + bias[ng]);
                    dst[1] = to_tf32(c1 + bias[ng + 1]);
                } else {
                    g_Vt[((size_t)(bb * 16 + hh) * 64 + dd    ) * 768 + l] = to_tf32(c0 + bias[ng]);
                    g_Vt[((size_t)(bb * 16 + hh) * 64 + dd + 1) * 768 + l] = to_tf32(c1 + bias[ng + 1]);
                }
            }
        }
    }
}

// ---------------------------------------------------------------------------
// Output projection: k-permuted (g_O2 D-permuted by av, Wo permuted by conv),
// LDS.64 fragments, stride-40 smem, plain fp32 OUT.
// ---------------------------------------------------------------------------
__global__ __launch_bounds__(256)
void proj_out(const float* __restrict__ bias, float* __restrict__ OUT)
{
    extern __shared__ float sm[];
    const uint32_t smb = smem_u32(sm);
    constexpr int STG = 2 * 128 * 40;

    const int tid = threadIdx.x, lane = tid & 31, wid = tid >> 5;
    const int g4 = lane >> 2, cq = lane & 3;
    const int wm = (wid & 1) * 64, wn = (wid >> 1) * 32;

    const float* Arow = g_O2 + (size_t)(blockIdx.y * 128) * 1024;
    const float* Brow = g_Wo + (size_t)(blockIdx.x * 128) * 1024;

    auto loadAB = [&](int t, int s) {
        const uint32_t base = smb + (uint32_t)s * STG * 4;
        const int k0 = t * 32;
#pragma unroll
        for (int i = 0; i < 4; ++i) {
            int idx = tid + i * 256;
            int r = idx >> 3, seg = idx & 7;
            CP_A16(base + (uint32_t)(r * 40 + seg * 4) * 4,
                   Arow + (size_t)r * 1024 + k0 + seg * 4);
        }
#pragma unroll
        for (int i = 0; i < 4; ++i) {
            int idx = tid + i * 256;
            int r = idx >> 3, seg = idx & 7;
            CP_A16(base + (uint32_t)(128 * 40 + r * 40 + seg * 4) * 4,
                   Brow + (size_t)r * 1024 + k0 + seg * 4);
        }
    };

    float acc[4][4][4] = {};

    loadAB(0, 0); CP_COMMIT();

    for (int t = 0; t < 32; ++t) {
        if (t + 1 < 32) { loadAB(t + 1, (t + 1) & 1); CP_COMMIT(); }
        if (t + 1 < 32) { CP_WAIT1(); } else { CP_WAIT0(); }
        __syncthreads();

        const float* As = sm + (t & 1) * STG;
        const float* Bs = As + 128 * 40;
#pragma unroll
        for (int ks = 0; ks < 4; ++ks) {
            uint32_t afr[4][4], bfr[4][2];
#pragma unroll
            for (int m = 0; m < 4; ++m) {
                const float* p = As + (wm + m * 16 + g4) * 40 + ks * 8 + 2 * cq;
                float2 lo = *(const float2*)p;
                float2 hi = *(const float2*)(p + 8 * 40);
                afr[m][0] = __float_as_uint(lo.x);
                afr[m][1] = __float_as_uint(hi.x);
                afr[m][2] = __float_as_uint(lo.y);
                afr[m][3] = __float_as_uint(hi.y);
            }
#pragma unroll
            for (int n = 0; n < 4; ++n) {
                const float* p = Bs + (wn + n * 8 + g4) * 40 + ks * 8 + 2 * cq;
                float2 b = *(const float2*)p;
                bfr[n][0] = __float_as_uint(b.x);
                bfr[n][1] = __float_as_uint(b.y);
            }
#pragma unroll
            for (int m = 0; m < 4; ++m)
#pragma unroll
                for (int n = 0; n < 4; ++n)
                    mma_tf32(acc[m][n], afr[m], bfr[n]);
        }
        __syncthreads();
    }

#pragma unroll
    for (int m = 0; m < 4; ++m) {
#pragma unroll
        for (int n = 0; n < 4; ++n) {
            const int col = wn + n * 8 + cq * 2;
#pragma unroll
            for (int h2 = 0; h2 < 2; ++h2) {
                const int row = wm + m * 16 + g4 + h2 * 8;
                const int mg = blockIdx.y * 128 + row;
                const int ng = blockIdx.x * 128 + col;
                float* dst = OUT + (size_t)mg * 1024 + ng;
                dst[0] = acc[m][n][h2 * 2 + 0] + bias[ng];
                dst[1] = acc[m][n][h2 * 2 + 1] + bias[ng + 1];
            }
        }
    }
}

// ---------------------------------------------------------------------------
// Fused scores + rel + exp + rowsum (R7-proven, untouched). CTA per (qt, bh).
// ---------------------------------------------------------------------------
__global__ __launch_bounds__(256)
void scores_fused()
{
    extern __shared__ float sm[];
    float* Bbuf = sm;                       // [2][128*68]
    float* Wbuf = sm + 2 * 128 * 68;        // [2][128*132]
    const uint32_t bb_a = smem_u32(Bbuf);
    const uint32_t wq_a = smem_u32(Wbuf);
    __shared__ float ssum[128];

    const int tid  = threadIdx.x;
    const int lane = tid & 31, wid = tid >> 5;
    const int g4 = lane >> 2, cq = lane & 3;
    const int wm = (wid & 3) * 32, wn = (wid >> 2) * 64;
    const int qt = blockIdx.x, bh = blockIdx.y;

    if (tid < 128) ssum[tid] = 0.f;

    const float* Qg = g_Qp + ((size_t)bh * 768 + qt * 128) * 64;
    const float* Kg = g_Kp + (size_t)bh * 768 * 64;
    const int base0 = 640 - qt * 128;

#pragma unroll
    for (int i = 0; i < 8; ++i) {
        int idx = tid + i * 256;
        int r = idx >> 4, seg = idx & 15;
        CP_A16(wq_a + (uint32_t)(r * 68 + seg * 4) * 4, Qg + r * 64 + seg * 4);
    }
    CP_COMMIT();

    auto loadB = [&](int i) {
        const uint32_t base = bb_a + (uint32_t)(i & 1) * (128 * 68 * 4);
        const bool content = (i >= 2) && ((i & 1) == 0);
        if (content) {
            const int xt = (i - 2) >> 1;
            const float* s0 = Kg + (size_t)xt * 128 * 64;
#pragma unroll
            for (int k = 0; k < 8; ++k) {
                int idx = tid + k * 256;
                int r = idx >> 4, seg = idx & 15;
                CP_A16(base + (uint32_t)(r * 68 + seg * 4) * 4, s0 + r * 64 + seg * 4);
            }
        } else {
            const int w = (i < 2) ? i : ((i + 1) >> 1);
            const int jb = base0 + w * 128;
#pragma unroll
            for (int k = 0; k < 8; ++k) {
                int idx = tid + k * 256;
                int r = idx >> 4, seg = idx & 15;
                int j = jb + r;
                int jc = (j > 1534) ? 1534 : j;
                unsigned sz = (j <= 1534) ? 16u : 0u;
                CP_A16Z(base + (uint32_t)(r * 68 + seg * 4) * 4,
                        g_Ec + (size_t)jc * 64 + seg * 4, sz);
            }
        }
    };

    loadB(0); CP_COMMIT();
    loadB(1); CP_COMMIT();

    CP_WAIT2();
    __syncthreads();

    uint32_t afr[8][2][4];
#pragma unroll
    for (int ks = 0; ks < 8; ++ks)
#pragma unroll
        for (int mt = 0; mt < 2; ++mt) {
            const float* q = Wbuf + (wm + mt * 16 + g4) * 68 + ks * 8 + cq;
            afr[ks][mt][0] = __float_as_uint(q[0]);
            afr[ks][mt][1] = __float_as_uint(q[8 * 68]);
            afr[ks][mt][2] = __float_as_uint(q[4]);
            afr[ks][mt][3] = __float_as_uint(q[8 * 68 + 4]);
        }
    __syncthreads();

    CP_WAIT1();
    __syncthreads();

    float rsum[4] = {0.f, 0.f, 0.f, 0.f};

#pragma unroll 1
    for (int i = 0; i < 13; ++i) {
        const float* Bsb = Bbuf + (i & 1) * (128 * 68);
        float acc[2][8][4] = {};

#pragma unroll
        for (int ks = 0; ks < 8; ++ks) {
            uint32_t bfr[8][2];
#pragma unroll
            for (int nt = 0; nt < 8; ++nt) {
                const float* b = Bsb + (wn + nt * 8 + g4) * 68 + ks * 8 + cq;
                bfr[nt][0] = __float_as_uint(b[0]);
                bfr[nt][1] = __float_as_uint(b[4]);
            }
#pragma unroll
            for (int mt = 0; mt < 2; ++mt)
#pragma unroll
                for (int nt = 0; nt < 8; ++nt)
                    mma_tf32(acc[mt][nt], afr[ks][mt], bfr[nt]);
        }

        const bool content = (i >= 2) && ((i & 1) == 0);
        if (!content) {
            const int w = (i < 2) ? i : ((i + 1) >> 1);
            float* Wd = Wbuf + (w & 1) * (128 * 132);
#pragma unroll
            for (int mt = 0; mt < 2; ++mt)
#pragma unroll
                for (int h2 = 0; h2 < 2; ++h2) {
                    const int row = wm + mt * 16 + g4 + h2 * 8;
#pragma unroll
                    for (int nt = 0; nt < 8; ++nt) {
                        const int col = wn + nt * 8 + 2 * cq;
                        Wd[row * 132 + col    ] = acc[mt][nt][h2 * 2 + 0];
                        Wd[row * 132 + col + 1] = acc[mt][nt][h2 * 2 + 1];
                    }
                }
        } else {
            const int xt = (i - 2) >> 1;
            const float* W0 = Wbuf + (xt & 1) * (128 * 132);
            const float* W1 = Wbuf + ((xt + 1) & 1) * (128 * 132);
            float* Sd = g_S + ((size_t)bh * 768 + qt * 128) * 768 + xt * 128;
#pragma unroll
            for (int mt = 0; mt < 2; ++mt)
#pragma unroll
                for (int h2 = 0; h2 < 2; ++h2) {
                    const int row = wm + mt * 16 + g4 + h2 * 8;
                    float rs = 0.f;
#pragma unroll
                    for (int nt = 0; nt < 8; ++nt) {
                        const int col = wn + nt * 8 + 2 * cq;
                        const int c0 = col - row + 127;
                        const int c1 = c0 + 1;
                        const float r0 = (c0 < 128) ? W0[row * 132 + c0]
                                                    : W1[row * 132 + c0 - 128];
                        const float r1 = (c1 < 128) ? W0[row * 132 + c1]
                                                    : W1[row * 132 + c1 - 128];
                        const float p0 = __expf(SCALE * (acc[mt][nt][h2 * 2 + 0] + r0));
                        const float p1 = __expf(SCALE * (acc[mt][nt][h2 * 2 + 1] + r1));
                        rs += p0 + p1;
                        *(float2*)&Sd[(size_t)row * 768 + col] =
                            make_float2(to_tf32(p0), to_tf32(p1));
                    }
                    rsum[mt * 2 + h2] += rs;
                }
        }

        __syncthreads();
        if (i + 2 < 13) { loadB(i + 2); CP_COMMIT(); }
        if (i + 1 < 13) {
            if (i + 2 < 13) { CP_WAIT1(); } else { CP_WAIT0(); }
            __syncthreads();
        }
    }

#pragma unroll
    for (int k = 0; k < 4; ++k) {
        rsum[k] += __shfl_xor_sync(0xffffffffu, rsum[k], 1);
        rsum[k] += __shfl_xor_sync(0xffffffffu, rsum[k], 2);
    }
    __syncthreads();
    if (cq == 0) {
#pragma unroll
        for (int k = 0; k < 4; ++k) {
            const int row = wm + (k >> 1) * 16 + g4 + (k & 1) * 8;
            atomicAdd(&ssum[row], rsum[k]);
        }
    }
    __syncthreads();
    if (tid < 128)
        g_InvSum[bh * 768 + qt * 128 + tid] = 1.0f / ssum[tid];
}

// ---------------------------------------------------------------------------
// AV GEMM (R10-proven 256-thread version): C[128,64] = P @ Vt^T per (qt,bh).
// Epilogue normalizes by InvSum and writes g_O2 with D-permuted columns
// (so proj_out's k-permuted pipeline matches).
// ---------------------------------------------------------------------------
__global__ __launch_bounds__(256)
void av_mma()
{
    extern __shared__ float sm[];
    constexpr int ASZ = 128 * 68, BSZ = 64 * 68, STG = ASZ + BSZ;
    const uint32_t smb = smem_u32(sm);

    const int tid = threadIdx.x, lane = tid & 31, wid = tid >> 5;
    const int g4 = lane >> 2, cq = lane & 3;
    const int wm = (wid & 3) * 32, wn = (wid >> 2) * 32;
    const int qt = blockIdx.x, bh = blockIdx.y;

    const float* P = g_S  + ((size_t)bh * 768 + qt * 128) * 768;
    const float* V = g_Vt + (size_t)bh * 64 * 768;

    auto load = [&](int t, int s) {
        const uint32_t base = smb + (uint32_t)s * STG * 4;
        const int k0 = t * 64;
#pragma unroll
        for (int i = 0; i < 8; ++i) {
            int idx = tid + i * 256;
            int r = idx >> 4, seg = idx & 15;
            CP_A16(base + (uint32_t)(r * 68 + seg * 4) * 4,
                   P + (size_t)r * 768 + k0 + seg * 4);
        }
#pragma unroll
        for (int i = 0; i < 4; ++i) {
            int idx = tid + i * 256;
            int r = idx >> 4, seg = idx & 15;
            CP_A16(base + (uint32_t)(ASZ + r * 68 + seg * 4) * 4,
                   V + (size_t)r * 768 + k0 + seg * 4);
        }
    };

    float acc[2][4][4] = {};

    load(0, 0); CP_COMMIT();
    load(1, 1); CP_COMMIT();
    CP_WAIT1();
    __syncthreads();

#pragma unroll 1
    for (int t = 0; t < 12; ++t) {
        const float* As = sm + (t & 1) * STG;
        const float* Bs = As + ASZ;
#pragma unroll
        for (int ks = 0; ks < 8; ++ks) {
            uint32_t afr[2][4], bfr[4][2];
#pragma unroll
            for (int mt = 0; mt < 2; ++mt) {
                const float* p = As + (wm + mt * 16 + g4) * 68 + ks * 8 + cq;
                afr[mt][0] = __float_as_uint(p[0]);
                afr[mt][1] = __float_as_uint(p[8 * 68]);
                afr[mt][2] = __float_as_uint(p[4]);
                afr[mt][3] = __float_as_uint(p[8 * 68 + 4]);
            }
#pragma unroll
            for (int nt = 0; nt < 4; ++nt) {
                const float* p = Bs + (wn + nt * 8 + g4) * 68 + ks * 8 + cq;
                bfr[nt][0] = __float_as_uint(p[0]);
                bfr[nt][1] = __float_as_uint(p[4]);
            }
#pragma unroll
            for (int mt = 0; mt < 2; ++mt)
#pragma unroll
                for (int nt = 0; nt < 4; ++nt)
                    mma_tf32(acc[mt][nt], afr[mt], bfr[nt]);
        }
        __syncthreads();
        if (t + 2 < 12) { load(t + 2, t & 1); CP_COMMIT(); }
        if (t + 1 < 12) {
            if (t + 2 < 12) { CP_WAIT1(); } else { CP_WAIT0(); }
            __syncthreads();
        }
    }

    const int b = bh >> 4, h = bh & 15;
    // permutation of the low-3 bits for the D dimension
    const int j0 = 2 * cq;
    const int p0 = (j0 & 3) * 2 + (j0 >> 2);
    const int p1 = ((j0 + 1) & 3) * 2 + ((j0 + 1) >> 2);
#pragma unroll
    for (int mt = 0; mt < 2; ++mt)
#pragma unroll
        for (int h2 = 0; h2 < 2; ++h2) {
            const int row = wm + mt * 16 + g4 + h2 * 8;
            const float inv = g_InvSum[bh * 768 + qt * 128 + row];
#pragma unroll
            for (int nt = 0; nt < 4; ++nt) {
                const int colbase = wn + nt * 8;
                float* dst = g_O2 + ((size_t)(b * 768) + qt * 128 + row) * 1024
                             + h * 64 + colbase;
                dst[p0] = to_tf32(acc[mt][nt][h2 * 2 + 0] * inv);
                dst[p1] = to_tf32(acc[mt][nt][h2 * 2 + 1] * inv);
            }
        }
}

// ---------------------------------------------------------------------------
extern "C" void kernel_launch(void* const* d_in, const int* in_sizes, int n_in,
                              void* d_out, int out_size)
{
    const float* query = (const float*)d_in[0];
    const float* key   = (const float*)d_in[1];
    const float* value = (const float*)d_in[2];
    const float* w_q   = (const float*)d_in[3];
    const float* b_q   = (const float*)d_in[4];
    const float* w_k   = (const float*)d_in[5];
    const float* b_k   = (const float*)d_in[6];
    const float* w_v   = (const float*)d_in[7];
    const float* b_v   = (const float*)d_in[8];
    const float* w_o   = (const float*)d_in[9];
    const float* b_o   = (const float*)d_in[10];
    const float* relE  = (const float*)d_in[11];
    float* out = (float*)d_out;

    float *xr, *wq, *wk, *wv, *wo, *qp, *kp, *ec;
    cudaGetSymbolAddress((void**)&xr, g_Xr);
    cudaGetSymbolAddress((void**)&wq, g_Wq);
    cudaGetSymbolAddress((void**)&wk, g_Wk);
    cudaGetSymbolAddress((void**)&wv, g_Wv);
    cudaGetSymbolAddress((void**)&wo, g_Wo);
    cudaGetSymbolAddress((void**)&qp, g_Qp);
    cudaGetSymbolAddress((void**)&kp, g_Kp);
    cudaGetSymbolAddress((void**)&ec, g_Ec);

    const int SMEMP   = 2 * 2 * 128 * 40 * 4;                    // 81920
    const int SC_SMEM = (2 * 128 * 68 + 2 * 128 * 132) * 4;      // 204800
    const int AV_SMEM = 2 * (128 * 68 + 64 * 68) * 4;            // 104448
    cudaFuncSetAttribute(proj_qkv, cudaFuncAttributeMaxDynamicSharedMemorySize, SMEMP);
    cudaFuncSetAttribute(proj_out, cudaFuncAttributeMaxDynamicSharedMemorySize, SMEMP);
    cudaFuncSetAttribute(scores_fused, cudaFuncAttributeMaxDynamicSharedMemorySize, SC_SMEM);
    cudaFuncSetAttribute(av_mma,       cudaFuncAttributeMaxDynamicSharedMemorySize, AV_SMEM);

    const int NW4 = 1024 * 1024 / 4;
    const int NE4 = 1535 * 64 / 4;
    const int NX4 = M_ * D_ / 4;

    // weights (k-permuted) + rel embedding (plain), 5-way z-batched
    conv_w<<<dim3((NW4 + 255) / 256, 1, 5), 256>>>(
        (const float4*)w_q, (const float4*)w_k, (const float4*)w_v,
        (const float4*)w_o, (const float4*)relE,
        wq, wk, wv, wo, (float4*)ec, NW4, NE4);

    // inputs (k-permuted), 3-way z-batched into g_Xr[0..2]
    conv_x<<<dim3((NX4 + 255) / 256, 1, 3), 256>>>(
        (const float4*)query, (const float4*)key, (const float4*)value,
        xr, xr + M_ * D_, xr + 2 * M_ * D_, NX4);

    proj_qkv<<<dim3(8, 48, 3), 256, SMEMP>>>(b_q, b_k, b_v, qp, kp);

    scores_fused<<<dim3(6, 128), 256, SC_SMEM>>>();
    av_mma<<<dim3(6, 128), 256, AV_SMEM>>>();

    proj_out<<<dim3(8, 48), 256, SMEMP>>>(b_o, out);
}

// round 13
// speedup vs baseline: 1.1607x; 1.1522x over previous
#include <cuda_runtime.h>
#include <cuda_bf16.h>
#include <cstdint>

#define B_    8
#define L_    768
#define H_    16
#define DK_   64
#define D_    1024
#define BH_   128
#define M_    6144
#define SCALE 0.125f

// Scratch (device globals; allocation forbidden)
__device__ float g_Xr[3][M_ * D_];                     // tf32 inputs, k-permuted
__device__ float g_Wq[D_ * D_], g_Wk[D_ * D_], g_Wv[D_ * D_], g_Wo[D_ * D_];
__device__ float g_Qp[BH_ * L_ * DK_];                 // [bh][l][dk] tf32
__device__ float g_Kp[BH_ * L_ * DK_];                 // tf32
__device__ float g_Vt[BH_ * DK_ * L_];                 // V^T [bh][dk][l] tf32
__device__ __nv_bfloat16 g_Ec[1535 * 64];              // bf16 rel embedding
__device__ float g_S [(size_t)BH_ * L_ * L_];          // unnormalized probs (tf32)
__device__ float g_InvSum[BH_ * L_];                   // 1/rowsum
__device__ float g_O2[(size_t)M_ * D_];                // attn out, merged, tf32, D-permuted

__device__ __forceinline__ float to_tf32(float x) {
    float r;
    asm("cvt.rna.tf32.f32 %0, %1;" : "=f"(r) : "f"(x));
    return r;
}
__device__ __forceinline__ uint32_t pack_bf16(float lo, float hi) {
    uint32_t r;
    asm("cvt.rn.bf16x2.f32 %0, %1, %2;" : "=r"(r) : "f"(hi), "f"(lo));
    return r;
}
__device__ __forceinline__ uint32_t smem_u32(const void* p) {
    uint32_t a;
    asm("{ .reg .u64 t; cvta.to.shared.u64 t, %1; cvt.u32.u64 %0, t; }"
        : "=r"(a) : "l"(p));
    return a;
}
__device__ __forceinline__ void mma_tf32(float* d, const uint32_t* a, const uint32_t* b) {
    asm volatile(
        "mma.sync.aligned.m16n8k8.row.col.f32.tf32.tf32.f32 "
        "{%0,%1,%2,%3}, {%4,%5,%6,%7}, {%8,%9}, {%0,%1,%2,%3};"
        : "+f"(d[0]), "+f"(d[1]), "+f"(d[2]), "+f"(d[3])
        : "r"(a[0]), "r"(a[1]), "r"(a[2]), "r"(a[3]), "r"(b[0]), "r"(b[1]));
}
__device__ __forceinline__ void mma_bf16(float* d, const uint32_t* a, const uint32_t* b) {
    asm volatile(
        "mma.sync.aligned.m16n8k16.row.col.f32.bf16.bf16.f32 "
        "{%0,%1,%2,%3}, {%4,%5,%6,%7}, {%8,%9}, {%0,%1,%2,%3};"
        : "+f"(d[0]), "+f"(d[1]), "+f"(d[2]), "+f"(d[3])
        : "r"(a[0]), "r"(a[1]), "r"(a[2]), "r"(a[3]), "r"(b[0]), "r"(b[1]));
}
#define CP_A16(dst, src) \
    asm volatile("cp.async.ca.shared.global [%0], [%1], 16;" :: "r"(dst), "l"(src) : "memory")
#define CP_A16Z(dst, src, sz) \
    asm volatile("cp.async.ca.shared.global [%0], [%1], 16, %2;" :: "r"(dst), "l"(src), "r"(sz) : "memory")
#define CP_COMMIT() asm volatile("cp.async.commit_group;" ::: "memory")
#define CP_WAIT2()  asm volatile("cp.async.wait_group 2;" ::: "memory")
#define CP_WAIT1()  asm volatile("cp.async.wait_group 1;" ::: "memory")
#define CP_WAIT0()  asm volatile("cp.async.wait_group 0;" ::: "memory")

// ---------------------------------------------------------------------------
// Conversions. Weights: tf32 + within-8 k-permutation. E: bf16 (no permute).
// ---------------------------------------------------------------------------
__global__ __launch_bounds__(256)
void conv_w(const float4* __restrict__ p0, const float4* __restrict__ p1,
            const float4* __restrict__ p2, const float4* __restrict__ p3,
            const float4* __restrict__ p4,
            float* __restrict__ d0, float* __restrict__ d1,
            float* __restrict__ d2, float* __restrict__ d3,
            __nv_bfloat16* __restrict__ d4, int n4w, int n4e)
{
    const int z = blockIdx.z;
    int i = blockIdx.x * 256 + threadIdx.x;
    if (z == 4) {
        if (i < n4e) {
            float4 v = p4[i];
            __nv_bfloat16* o = d4 + i * 4;
            o[0] = __float2bfloat16(v.x);
            o[1] = __float2bfloat16(v.y);
            o[2] = __float2bfloat16(v.z);
            o[3] = __float2bfloat16(v.w);
        }
        return;
    }
    const float4* in = (z == 0) ? p0 : (z == 1) ? p1 : (z == 2) ? p2 : p3;
    float*       out = (z == 0) ? d0 : (z == 1) ? d1 : (z == 2) ? d2 : d3;
    if (i < n4w) {
        float4 v = in[i];
        const int base = (i >> 1) * 8 + (i & 1);
        out[base + 0] = to_tf32(v.x);
        out[base + 2] = to_tf32(v.y);
        out[base + 4] = to_tf32(v.z);
        out[base + 6] = to_tf32(v.w);
    }
}
__global__ __launch_bounds__(256)
void conv_x(const float4* __restrict__ p0, const float4* __restrict__ p1,
            const float4* __restrict__ p2,
            float* __restrict__ d0, float* __restrict__ d1,
            float* __restrict__ d2, int n4)
{
    const int z = blockIdx.z;
    const float4* in = (z == 0) ? p0 : (z == 1) ? p1 : p2;
    float*       out = (z == 0) ? d0 : (z == 1) ? d1 : d2;
    int i = blockIdx.x * 256 + threadIdx.x;
    if (i < n4) {
        float4 v = in[i];
        const int base = (i >> 1) * 8 + (i & 1);
        out[base + 0] = to_tf32(v.x);
        out[base + 2] = to_tf32(v.y);
        out[base + 4] = to_tf32(v.z);
        out[base + 6] = to_tf32(v.w);
    }
}

// ---------------------------------------------------------------------------
// QKV projection (R12-proven). k-permuted operands, LDS.64 frags, stride-40.
// ---------------------------------------------------------------------------
__global__ __launch_bounds__(256)
void proj_qkv(const float* __restrict__ bq, const float* __restrict__ bk,
              const float* __restrict__ bv, float* __restrict__ Qout,
              float* __restrict__ Kout)
{
    extern __shared__ float sm[];
    const uint32_t smb = smem_u32(sm);
    constexpr int STG = 2 * 128 * 40;

    const int tid = threadIdx.x, lane = tid & 31, wid = tid >> 5;
    const int g4 = lane >> 2, cq = lane & 3;
    const int wm = (wid & 1) * 64, wn = (wid >> 1) * 32;
    const int z = blockIdx.z;

    const float* Ag = g_Xr[z];
    const float* Bg = (z == 0) ? g_Wq : (z == 1) ? g_Wk : g_Wv;
    const float* bias = (z == 0) ? bq : (z == 1) ? bk : bv;

    const float* Arow = Ag + (size_t)(blockIdx.y * 128) * 1024;
    const float* Brow = Bg + (size_t)(blockIdx.x * 128) * 1024;

    auto loadAB = [&](int t, int s) {
        const uint32_t base = smb + (uint32_t)s * STG * 4;
        const int k0 = t * 32;
#pragma unroll
        for (int i = 0; i < 4; ++i) {
            int idx = tid + i * 256;
            int r = idx >> 3, seg = idx & 7;
            CP_A16(base + (uint32_t)(r * 40 + seg * 4) * 4,
                   Arow + (size_t)r * 1024 + k0 + seg * 4);
        }
#pragma unroll
        for (int i = 0; i < 4; ++i) {
            int idx = tid + i * 256;
            int r = idx >> 3, seg = idx & 7;
            CP_A16(base + (uint32_t)(128 * 40 + r * 40 + seg * 4) * 4,
                   Brow + (size_t)r * 1024 + k0 + seg * 4);
        }
    };

    float acc[4][4][4] = {};

    loadAB(0, 0); CP_COMMIT();

    for (int t = 0; t < 32; ++t) {
        if (t + 1 < 32) { loadAB(t + 1, (t + 1) & 1); CP_COMMIT(); }
        if (t + 1 < 32) { CP_WAIT1(); } else { CP_WAIT0(); }
        __syncthreads();

        const float* As = sm + (t & 1) * STG;
        const float* Bs = As + 128 * 40;
#pragma unroll
        for (int ks = 0; ks < 4; ++ks) {
            uint32_t afr[4][4], bfr[4][2];
#pragma unroll
            for (int m = 0; m < 4; ++m) {
                const float* p = As + (wm + m * 16 + g4) * 40 + ks * 8 + 2 * cq;
                float2 lo = *(const float2*)p;
                float2 hi = *(const float2*)(p + 8 * 40);
                afr[m][0] = __float_as_uint(lo.x);
                afr[m][1] = __float_as_uint(hi.x);
                afr[m][2] = __float_as_uint(lo.y);
                afr[m][3] = __float_as_uint(hi.y);
            }
#pragma unroll
            for (int n = 0; n < 4; ++n) {
                const float* p = Bs + (wn + n * 8 + g4) * 40 + ks * 8 + 2 * cq;
                float2 b = *(const float2*)p;
                bfr[n][0] = __float_as_uint(b.x);
                bfr[n][1] = __float_as_uint(b.y);
            }
#pragma unroll
            for (int m = 0; m < 4; ++m)
#pragma unroll
                for (int n = 0; n < 4; ++n)
                    mma_tf32(acc[m][n], afr[m], bfr[n]);
        }
        __syncthreads();
    }

    float* OUT = (z == 0) ? Qout : Kout;
#pragma unroll
    for (int m = 0; m < 4; ++m) {
#pragma unroll
        for (int n = 0; n < 4; ++n) {
            const int col = wn + n * 8 + cq * 2;
#pragma unroll
            for (int h2 = 0; h2 < 2; ++h2) {
                const int row = wm + m * 16 + g4 + h2 * 8;
                const float c0 = acc[m][n][h2 * 2 + 0];
                const float c1 = acc[m][n][h2 * 2 + 1];
                const int mg = blockIdx.y * 128 + row;
                const int ng = blockIdx.x * 128 + col;
                const int bb = mg / 768, l = mg - bb * 768;
                const int hh = ng >> 6, dd = ng & 63;
                if (z < 2) {
                    float* dst = OUT + (((size_t)(bb * 16 + hh) * 768) + l) * 64 + dd;
                    dst[0] = to_tf32(c0 + bias[ng]);
                    dst[1] = to_tf32(c1 + bias[ng + 1]);
                } else {
                    g_Vt[((size_t)(bb * 16 + hh) * 64 + dd    ) * 768 + l] = to_tf32(c0 + bias[ng]);
                    g_Vt[((size_t)(bb * 16 + hh) * 64 + dd + 1) * 768 + l] = to_tf32(c1 + bias[ng + 1]);
                }
            }
        }
    }
}

// ---------------------------------------------------------------------------
// Output projection (R12-proven).
// ---------------------------------------------------------------------------
__global__ __launch_bounds__(256)
void proj_out(const float* __restrict__ bias, float* __restrict__ OUT)
{
    extern __shared__ float sm[];
    const uint32_t smb = smem_u32(sm);
    constexpr int STG = 2 * 128 * 40;

    const int tid = threadIdx.x, lane = tid & 31, wid = tid >> 5;
    const int g4 = lane >> 2, cq = lane & 3;
    const int wm = (wid & 1) * 64, wn = (wid >> 1) * 32;

    const float* Arow = g_O2 + (size_t)(blockIdx.y * 128) * 1024;
    const float* Brow = g_Wo + (size_t)(blockIdx.x * 128) * 1024;

    auto loadAB = [&](int t, int s) {
        const uint32_t base = smb + (uint32_t)s * STG * 4;
        const int k0 = t * 32;
#pragma unroll
        for (int i = 0; i < 4; ++i) {
            int idx = tid + i * 256;
            int r = idx >> 3, seg = idx & 7;
            CP_A16(base + (uint32_t)(r * 40 + seg * 4) * 4,
                   Arow + (size_t)r * 1024 + k0 + seg * 4);
        }
#pragma unroll
        for (int i = 0; i < 4; ++i) {
            int idx = tid + i * 256;
            int r = idx >> 3, seg = idx & 7;
            CP_A16(base + (uint32_t)(128 * 40 + r * 40 + seg * 4) * 4,
                   Brow + (size_t)r * 1024 + k0 + seg * 4);
        }
    };

    float acc[4][4][4] = {};

    loadAB(0, 0); CP_COMMIT();

    for (int t = 0; t < 32; ++t) {
        if (t + 1 < 32) { loadAB(t + 1, (t + 1) & 1); CP_COMMIT(); }
        if (t + 1 < 32) { CP_WAIT1(); } else { CP_WAIT0(); }
        __syncthreads();

        const float* As = sm + (t & 1) * STG;
        const float* Bs = As + 128 * 40;
#pragma unroll
        for (int ks = 0; ks < 4; ++ks) {
            uint32_t afr[4][4], bfr[4][2];
#pragma unroll
            for (int m = 0; m < 4; ++m) {
                const float* p = As + (wm + m * 16 + g4) * 40 + ks * 8 + 2 * cq;
                float2 lo = *(const float2*)p;
                float2 hi = *(const float2*)(p + 8 * 40);
                afr[m][0] = __float_as_uint(lo.x);
                afr[m][1] = __float_as_uint(hi.x);
                afr[m][2] = __float_as_uint(lo.y);
                afr[m][3] = __float_as_uint(hi.y);
            }
#pragma unroll
            for (int n = 0; n < 4; ++n) {
                const float* p = Bs + (wn + n * 8 + g4) * 40 + ks * 8 + 2 * cq;
                float2 b = *(const float2*)p;
                bfr[n][0] = __float_as_uint(b.x);
                bfr[n][1] = __float_as_uint(b.y);
            }
#pragma unroll
            for (int m = 0; m < 4; ++m)
#pragma unroll
                for (int n = 0; n < 4; ++n)
                    mma_tf32(acc[m][n], afr[m], bfr[n]);
        }
        __syncthreads();
    }

#pragma unroll
    for (int m = 0; m < 4; ++m) {
#pragma unroll
        for (int n = 0; n < 4; ++n) {
            const int col = wn + n * 8 + cq * 2;
#pragma unroll
            for (int h2 = 0; h2 < 2; ++h2) {
                const int row = wm + m * 16 + g4 + h2 * 8;
                const int mg = blockIdx.y * 128 + row;
                const int ng = blockIdx.x * 128 + col;
                float* dst = OUT + (size_t)mg * 1024 + ng;
                dst[0] = acc[m][n][h2 * 2 + 0] + bias[ng];
                dst[1] = acc[m][n][h2 * 2 + 1] + bias[ng + 1];
            }
        }
    }
}

// ---------------------------------------------------------------------------
// Fused scores: content tiles via tf32 MMA, rel-window tiles via bf16
// m16n8k16 MMA with bf16 E smem and bf16 window smem. One CTA per (qt, bh).
// Tile stream: w0, w1, c0, w2, c1, ..., w6, c5 (13 tiles).
// smem: Bbuf fp32 2x128x68 | Ebuf bf16 2x128x72 | Wbuf bf16 2x128x136.
// Q staged fp32 in Wbuf region before windows overwrite it.
// ---------------------------------------------------------------------------
__global__ __launch_bounds__(256)
void scores_fused()
{
    extern __shared__ float sm[];
    constexpr int BB_F = 128 * 68;                 // per-slot Bbuf floats
    constexpr int E_ELEM = 128 * 72;               // per-slot Ebuf bf16 elems
    constexpr int W_ELEM = 128 * 136;              // per-slot Wbuf bf16 elems
    float* Bbuf = sm;                              // 2 slots fp32
    __nv_bfloat16* Ebuf = (__nv_bfloat16*)(sm + 2 * BB_F);
    __nv_bfloat16* Wbuf = Ebuf + 2 * E_ELEM;
    float* Qstage = (float*)Wbuf;                  // fp32 staging, dead later
    const uint32_t bb_a = smem_u32(Bbuf);
    const uint32_t eb_a = smem_u32(Ebuf);
    const uint32_t wq_a = smem_u32(Qstage);
    __shared__ float ssum[128];

    const int tid  = threadIdx.x;
    const int lane = tid & 31, wid = tid >> 5;
    const int g4 = lane >> 2, cq = lane & 3;
    const int wm = (wid & 3) * 32, wn = (wid >> 2) * 64;
    const int qt = blockIdx.x, bh = blockIdx.y;

    if (tid < 128) ssum[tid] = 0.f;

    const float* Qg = g_Qp + ((size_t)bh * 768 + qt * 128) * 64;
    const float* Kg = g_Kp + (size_t)bh * 768 * 64;
    const int base0 = 640 - qt * 128;

    // stage Q (fp32) into Wbuf region
#pragma unroll
    for (int i = 0; i < 8; ++i) {
        int idx = tid + i * 256;
        int r = idx >> 4, seg = idx & 15;
        CP_A16(wq_a + (uint32_t)(r * 68 + seg * 4) * 4, Qg + r * 64 + seg * 4);
    }
    CP_COMMIT();

    auto loadTile = [&](int i) {
        const bool content = (i >= 2) && ((i & 1) == 0);
        if (content) {
            const int xt = (i - 2) >> 1;
            const uint32_t base = bb_a + (uint32_t)(xt & 1) * (BB_F * 4);
            const float* s0 = Kg + (size_t)xt * 128 * 64;
#pragma unroll
            for (int k = 0; k < 8; ++k) {
                int idx = tid + k * 256;
                int r = idx >> 4, seg = idx & 15;
                CP_A16(base + (uint32_t)(r * 68 + seg * 4) * 4, s0 + r * 64 + seg * 4);
            }
        } else {
            const int w = (i < 2) ? i : ((i + 1) >> 1);
            const uint32_t base = eb_a + (uint32_t)(w & 1) * (E_ELEM * 2);
            const int jb = base0 + w * 128;
#pragma unroll
            for (int k = 0; k < 4; ++k) {
                int idx = tid + k * 256;         // 1024 = 128 rows x 8 segs (16B)
                int r = idx >> 3, seg = idx & 7;
                int j = jb + r;
                int jc = (j > 1534) ? 1534 : j;
                unsigned sz = (j <= 1534) ? 16u : 0u;
                CP_A16Z(base + (uint32_t)(r * 72 + seg * 8) * 2,
                        g_Ec + (size_t)jc * 64 + seg * 8, sz);
            }
        }
    };

    loadTile(0); CP_COMMIT();
    loadTile(1); CP_COMMIT();

    CP_WAIT2();          // Q staged
    __syncthreads();

    // fp32 (tf32) Q fragments for content tiles: [ks8][mt][4]
    uint32_t afr[8][2][4];
#pragma unroll
    for (int ks = 0; ks < 8; ++ks)
#pragma unroll
        for (int mt = 0; mt < 2; ++mt) {
            const float* q = Qstage + (wm + mt * 16 + g4) * 68 + ks * 8 + cq;
            afr[ks][mt][0] = __float_as_uint(q[0]);
            afr[ks][mt][1] = __float_as_uint(q[8 * 68]);
            afr[ks][mt][2] = __float_as_uint(q[4]);
            afr[ks][mt][3] = __float_as_uint(q[8 * 68 + 4]);
        }
    // bf16 Q fragments for window tiles: [ks16][mt][4]
    uint32_t aqb[4][2][4];
#pragma unroll
    for (int ks = 0; ks < 4; ++ks)
#pragma unroll
        for (int mt = 0; mt < 2; ++mt) {
            const int row = wm + mt * 16 + g4;
            const float* q0 = Qstage + row * 68 + ks * 16;
            const float* q1 = Qstage + (row + 8) * 68 + ks * 16;
            float2 x0 = *(const float2*)(q0 + 2 * cq);
            float2 x1 = *(const float2*)(q0 + 2 * cq + 8);
            float2 y0 = *(const float2*)(q1 + 2 * cq);
            float2 y1 = *(const float2*)(q1 + 2 * cq + 8);
            aqb[ks][mt][0] = pack_bf16(x0.x, x0.y);
            aqb[ks][mt][1] = pack_bf16(y0.x, y0.y);
            aqb[ks][mt][2] = pack_bf16(x1.x, x1.y);
            aqb[ks][mt][3] = pack_bf16(y1.x, y1.y);
        }
    __syncthreads();     // Qstage dead; Wbuf may now be overwritten

    CP_WAIT1();          // tile 0 ready
    __syncthreads();

    float rsum[4] = {0.f, 0.f, 0.f, 0.f};

#pragma unroll 1
    for (int i = 0; i < 13; ++i) {
        const bool content = (i >= 2) && ((i & 1) == 0);
        float acc[2][8][4] = {};

        if (!content) {
            // ---- window tile: bf16 m16n8k16 MMA from Ebuf ----
            const int w = (i < 2) ? i : ((i + 1) >> 1);
            const uint32_t* Eb = (const uint32_t*)(Ebuf + (w & 1) * E_ELEM);
#pragma unroll
            for (int ks = 0; ks < 4; ++ks) {
                uint32_t bfr[8][2];
#pragma unroll
                for (int nt = 0; nt < 8; ++nt) {
                    const uint32_t* e = Eb + (wn + nt * 8 + g4) * 36 + ks * 8 + cq;
                    bfr[nt][0] = e[0];
                    bfr[nt][1] = e[4];
                }
#pragma unroll
                for (int mt = 0; mt < 2; ++mt)
#pragma unroll
                    for (int nt = 0; nt < 8; ++nt)
                        mma_bf16(acc[mt][nt], aqb[ks][mt], bfr[nt]);
            }
            // store window tile to Wbuf (bf16)
            __nv_bfloat16* Wd = Wbuf + (w & 1) * W_ELEM;
#pragma unroll
            for (int mt = 0; mt < 2; ++mt)
#pragma unroll
                for (int h2 = 0; h2 < 2; ++h2) {
                    const int row = wm + mt * 16 + g4 + h2 * 8;
#pragma unroll
                    for (int nt = 0; nt < 8; ++nt) {
                        const int col = wn + nt * 8 + 2 * cq;
                        *(uint32_t*)((char*)Wd + (size_t)(row * 136 + col) * 2) =
                            pack_bf16(acc[mt][nt][h2 * 2 + 0],
                                      acc[mt][nt][h2 * 2 + 1]);
                    }
                }
        } else {
            // ---- content tile: tf32 MMA from Bbuf ----
            const int xt = (i - 2) >> 1;
            const float* Bsb = Bbuf + (xt & 1) * BB_F;
#pragma unroll
            for (int ks = 0; ks < 8; ++ks) {
                uint32_t bfr[8][2];
#pragma unroll
                for (int nt = 0; nt < 8; ++nt) {
                    const float* b = Bsb + (wn + nt * 8 + g4) * 68 + ks * 8 + cq;
                    bfr[nt][0] = __float_as_uint(b[0]);
                    bfr[nt][1] = __float_as_uint(b[4]);
                }
#pragma unroll
                for (int mt = 0; mt < 2; ++mt)
#pragma unroll
                    for (int nt = 0; nt < 8; ++nt)
                        mma_tf32(acc[mt][nt], afr[ks][mt], bfr[nt]);
            }
            // epilogue: add rel (bf16 windows), exp, rowsum, store p
            const __nv_bfloat16* W0 = Wbuf + (xt & 1) * W_ELEM;
            const __nv_bfloat16* W1 = Wbuf + ((xt + 1) & 1) * W_ELEM;
            float* Sd = g_S + ((size_t)bh * 768 + qt * 128) * 768 + xt * 128;
#pragma unroll
            for (int mt = 0; mt < 2; ++mt)
#pragma unroll
                for (int h2 = 0; h2 < 2; ++h2) {
                    const int row = wm + mt * 16 + g4 + h2 * 8;
                    float rs = 0.f;
#pragma unroll
                    for (int nt = 0; nt < 8; ++nt) {
                        const int col = wn + nt * 8 + 2 * cq;
                        const int c0 = col - row + 127;
                        const int c1 = c0 + 1;
                        const float r0 = __bfloat162float(
                            (c0 < 128) ? W0[row * 136 + c0] : W1[row * 136 + c0 - 128]);
                        const float r1 = __bfloat162float(
                            (c1 < 128) ? W0[row * 136 + c1] : W1[row * 136 + c1 - 128]);
                        const float p0 = __expf(SCALE * (acc[mt][nt][h2 * 2 + 0] + r0));
                        const float p1 = __expf(SCALE * (acc[mt][nt][h2 * 2 + 1] + r1));
                        rs += p0 + p1;
                        *(float2*)&Sd[(size_t)row * 768 + col] =
                            make_float2(to_tf32(p0), to_tf32(p1));
                    }
                    rsum[mt * 2 + h2] += rs;
                }
        }

        __syncthreads();
        if (i + 2 < 13) { loadTile(i + 2); CP_COMMIT(); }
        if (i + 1 < 13) {
            if (i + 2 < 13) { CP_WAIT1(); } else { CP_WAIT0(); }
            __syncthreads();
        }
    }

#pragma unroll
    for (int k = 0; k < 4; ++k) {
        rsum[k] += __shfl_xor_sync(0xffffffffu, rsum[k], 1);
        rsum[k] += __shfl_xor_sync(0xffffffffu, rsum[k], 2);
    }
    __syncthreads();
    if (cq == 0) {
#pragma unroll
        for (int k = 0; k < 4; ++k) {
            const int row = wm + (k >> 1) * 16 + g4 + (k & 1) * 8;
            atomicAdd(&ssum[row], rsum[k]);
        }
    }
    __syncthreads();
    if (tid < 128)
        g_InvSum[bh * 768 + qt * 128 + tid] = 1.0f / ssum[tid];
}

// ---------------------------------------------------------------------------
// AV GEMM (R12-proven): epilogue normalizes; writes g_O2 D-permuted.
// ---------------------------------------------------------------------------
__global__ __launch_bounds__(256)
void av_mma()
{
    extern __shared__ float sm[];
    constexpr int ASZ = 128 * 68, BSZ = 64 * 68, STG = ASZ + BSZ;
    const uint32_t smb = smem_u32(sm);

    const int tid = threadIdx.x, lane = tid & 31, wid = tid >> 5;
    const int g4 = lane >> 2, cq = lane & 3;
    const int wm = (wid & 3) * 32, wn = (wid >> 2) * 32;
    const int qt = blockIdx.x, bh = blockIdx.y;

    const float* P = g_S  + ((size_t)bh * 768 + qt * 128) * 768;
    const float* V = g_Vt + (size_t)bh * 64 * 768;

    auto load = [&](int t, int s) {
        const uint32_t base = smb + (uint32_t)s * STG * 4;
        const int k0 = t * 64;
#pragma unroll
        for (int i = 0; i < 8; ++i) {
            int idx = tid + i * 256;
            int r = idx >> 4, seg = idx & 15;
            CP_A16(base + (uint32_t)(r * 68 + seg * 4) * 4,
                   P + (size_t)r * 768 + k0 + seg * 4);
        }
#pragma unroll
        for (int i = 0; i < 4; ++i) {
            int idx = tid + i * 256;
            int r = idx >> 4, seg = idx & 15;
            CP_A16(base + (uint32_t)(ASZ + r * 68 + seg * 4) * 4,
                   V + (size_t)r * 768 + k0 + seg * 4);
        }
    };

    float acc[2][4][4] = {};

    load(0, 0); CP_COMMIT();
    load(1, 1); CP_COMMIT();
    CP_WAIT1();
    __syncthreads();

#pragma unroll 1
    for (int t = 0; t < 12; ++t) {
        const float* As = sm + (t & 1) * STG;
        const float* Bs = As + ASZ;
#pragma unroll
        for (int ks = 0; ks < 8; ++ks) {
            uint32_t afr[2][4], bfr[4][2];
#pragma unroll
            for (int mt = 0; mt < 2; ++mt) {
                const float* p = As + (wm + mt * 16 + g4) * 68 + ks * 8 + cq;
                afr[mt][0] = __float_as_uint(p[0]);
                afr[mt][1] = __float_as_uint(p[8 * 68]);
                afr[mt][2] = __float_as_uint(p[4]);
                afr[mt][3] = __float_as_uint(p[8 * 68 + 4]);
            }
#pragma unroll
            for (int nt = 0; nt < 4; ++nt) {
                const float* p = Bs + (wn + nt * 8 + g4) * 68 + ks * 8 + cq;
                bfr[nt][0] = __float_as_uint(p[0]);
                bfr[nt][1] = __float_as_uint(p[4]);
            }
#pragma unroll
            for (int mt = 0; mt < 2; ++mt)
#pragma unroll
                for (int nt = 0; nt < 4; ++nt)
                    mma_tf32(acc[mt][nt], afr[mt], bfr[nt]);
        }
        __syncthreads();
        if (t + 2 < 12) { load(t + 2, t & 1); CP_COMMIT(); }
        if (t + 1 < 12) {
            if (t + 2 < 12) { CP_WAIT1(); } else { CP_WAIT0(); }
            __syncthreads();
        }
    }

    const int b = bh >> 4, h = bh & 15;
    const int j0 = 2 * cq;
    const int p0 = (j0 & 3) * 2 + (j0 >> 2);
    const int p1 = ((j0 + 1) & 3) * 2 + ((j0 + 1) >> 2);
#pragma unroll
    for (int mt = 0; mt < 2; ++mt)
#pragma unroll
        for (int h2 = 0; h2 < 2; ++h2) {
            const int row = wm + mt * 16 + g4 + h2 * 8;
            const float inv = g_InvSum[bh * 768 + qt * 128 + row];
#pragma unroll
            for (int nt = 0; nt < 4; ++nt) {
                const int colbase = wn + nt * 8;
                float* dst = g_O2 + ((size_t)(b * 768) + qt * 128 + row) * 1024
                             + h * 64 + colbase;
                dst[p0] = to_tf32(acc[mt][nt][h2 * 2 + 0] * inv);
                dst[p1] = to_tf32(acc[mt][nt][h2 * 2 + 1] * inv);
            }
        }
}

// ---------------------------------------------------------------------------
extern "C" void kernel_launch(void* const* d_in, const int* in_sizes, int n_in,
                              void* d_out, int out_size)
{
    const float* query = (const float*)d_in[0];
    const float* key   = (const float*)d_in[1];
    const float* value = (const float*)d_in[2];
    const float* w_q   = (const float*)d_in[3];
    const float* b_q   = (const float*)d_in[4];
    const float* w_k   = (const float*)d_in[5];
    const float* b_k   = (const float*)d_in[6];
    const float* w_v   = (const float*)d_in[7];
    const float* b_v   = (const float*)d_in[8];
    const float* w_o   = (const float*)d_in[9];
    const float* b_o   = (const float*)d_in[10];
    const float* relE  = (const float*)d_in[11];
    float* out = (float*)d_out;

    float *xr, *wq, *wk, *wv, *wo, *qp, *kp;
    __nv_bfloat16* ec;
    cudaGetSymbolAddress((void**)&xr, g_Xr);
    cudaGetSymbolAddress((void**)&wq, g_Wq);
    cudaGetSymbolAddress((void**)&wk, g_Wk);
    cudaGetSymbolAddress((void**)&wv, g_Wv);
    cudaGetSymbolAddress((void**)&wo, g_Wo);
    cudaGetSymbolAddress((void**)&qp, g_Qp);
    cudaGetSymbolAddress((void**)&kp, g_Kp);
    cudaGetSymbolAddress((void**)&ec, g_Ec);

    const int SMEMP   = 2 * 2 * 128 * 40 * 4;                    // 81920
    const int SC_SMEM = 2 * 128 * 68 * 4 + 2 * 128 * 72 * 2
                      + 2 * 128 * 136 * 2;                       // 176128
    const int AV_SMEM = 2 * (128 * 68 + 64 * 68) * 4;            // 104448
    cudaFuncSetAttribute(proj_qkv, cudaFuncAttributeMaxDynamicSharedMemorySize, SMEMP);
    cudaFuncSetAttribute(proj_out, cudaFuncAttributeMaxDynamicSharedMemorySize, SMEMP);
    cudaFuncSetAttribute(scores_fused, cudaFuncAttributeMaxDynamicSharedMemorySize, SC_SMEM);
    cudaFuncSetAttribute(av_mma,       cudaFuncAttributeMaxDynamicSharedMemorySize, AV_SMEM);

    const int NW4 = 1024 * 1024 / 4;
    const int NE4 = 1535 * 64 / 4;
    const int NX4 = M_ * D_ / 4;

    conv_w<<<dim3((NW4 + 255) / 256, 1, 5), 256>>>(
        (const float4*)w_q, (const float4*)w_k, (const float4*)w_v,
        (const float4*)w_o, (const float4*)relE,
        wq, wk, wv, wo, ec, NW4, NE4);

    conv_x<<<dim3((NX4 + 255) / 256, 1, 3), 256>>>(
        (const float4*)query, (const float4*)key, (const float4*)value,
        xr, xr + M_ * D_, xr + 2 * M_ * D_, NX4);

    proj_qkv<<<dim3(8, 48, 3), 256, SMEMP>>>(b_q, b_k, b_v, qp, kp);

    scores_fused<<<dim3(6, 128), 256, SC_SMEM>>>();
    av_mma<<<dim3(6, 128), 256, AV_SMEM>>>();

    proj_out<<<dim3(8, 48), 256, SMEMP>>>(b_o, out);
}

// round 14
// speedup vs baseline: 1.2952x; 1.1159x over previous
#include <cuda_runtime.h>
#include <cuda_bf16.h>
#include <cstdint>

#define B_    8
#define L_    768
#define H_    16
#define DK_   64
#define D_    1024
#define BH_   128
#define M_    6144
#define SCALE 0.125f

// Scratch (device globals; allocation forbidden)
__device__ float g_Xr[3][M_ * D_];                     // tf32 inputs, k-permuted
__device__ float g_Wq[D_ * D_], g_Wk[D_ * D_], g_Wv[D_ * D_], g_Wo[D_ * D_];
__device__ float g_Qp[BH_ * L_ * DK_];                 // [bh][l][dk] tf32
__device__ float g_Kp[BH_ * L_ * DK_];                 // tf32
__device__ float g_Vt[BH_ * DK_ * L_];                 // V^T [bh][dk][l] tf32
__device__ __nv_bfloat16 g_Ec[1535 * 64];              // bf16 rel embedding
__device__ float g_O2[(size_t)M_ * D_];                // attn out, merged, tf32, D-permuted

__device__ __forceinline__ float to_tf32(float x) {
    float r;
    asm("cvt.rna.tf32.f32 %0, %1;" : "=f"(r) : "f"(x));
    return r;
}
__device__ __forceinline__ uint32_t pack_bf16(float lo, float hi) {
    uint32_t r;
    asm("cvt.rn.bf16x2.f32 %0, %1, %2;" : "=r"(r) : "f"(hi), "f"(lo));
    return r;
}
__device__ __forceinline__ uint32_t smem_u32(const void* p) {
    uint32_t a;
    asm("{ .reg .u64 t; cvta.to.shared.u64 t, %1; cvt.u32.u64 %0, t; }"
        : "=r"(a) : "l"(p));
    return a;
}
__device__ __forceinline__ void mma_tf32(float* d, const uint32_t* a, const uint32_t* b) {
    asm volatile(
        "mma.sync.aligned.m16n8k8.row.col.f32.tf32.tf32.f32 "
        "{%0,%1,%2,%3}, {%4,%5,%6,%7}, {%8,%9}, {%0,%1,%2,%3};"
        : "+f"(d[0]), "+f"(d[1]), "+f"(d[2]), "+f"(d[3])
        : "r"(a[0]), "r"(a[1]), "r"(a[2]), "r"(a[3]), "r"(b[0]), "r"(b[1]));
}
__device__ __forceinline__ void mma_bf16(float* d, const uint32_t* a, const uint32_t* b) {
    asm volatile(
        "mma.sync.aligned.m16n8k16.row.col.f32.bf16.bf16.f32 "
        "{%0,%1,%2,%3}, {%4,%5,%6,%7}, {%8,%9}, {%0,%1,%2,%3};"
        : "+f"(d[0]), "+f"(d[1]), "+f"(d[2]), "+f"(d[3])
        : "r"(a[0]), "r"(a[1]), "r"(a[2]), "r"(a[3]), "r"(b[0]), "r"(b[1]));
}
#define CP_A16(dst, src) \
    asm volatile("cp.async.ca.shared.global [%0], [%1], 16;" :: "r"(dst), "l"(src) : "memory")
#define CP_A16Z(dst, src, sz) \
    asm volatile("cp.async.ca.shared.global [%0], [%1], 16, %2;" :: "r"(dst), "l"(src), "r"(sz) : "memory")
#define CP_COMMIT() asm volatile("cp.async.commit_group;" ::: "memory")
#define CP_WAIT2()  asm volatile("cp.async.wait_group 2;" ::: "memory")
#define CP_WAIT1()  asm volatile("cp.async.wait_group 1;" ::: "memory")
#define CP_WAIT0()  asm volatile("cp.async.wait_group 0;" ::: "memory")

// ---------------------------------------------------------------------------
// Conversions (R13-proven). Weights: tf32 + within-8 k-permutation. E: bf16.
// ---------------------------------------------------------------------------
__global__ __launch_bounds__(256)
void conv_w(const float4* __restrict__ p0, const float4* __restrict__ p1,
            const float4* __restrict__ p2, const float4* __restrict__ p3,
            const float4* __restrict__ p4,
            float* __restrict__ d0, float* __restrict__ d1,
            float* __restrict__ d2, float* __restrict__ d3,
            __nv_bfloat16* __restrict__ d4, int n4w, int n4e)
{
    const int z = blockIdx.z;
    int i = blockIdx.x * 256 + threadIdx.x;
    if (z == 4) {
        if (i < n4e) {
            float4 v = p4[i];
            __nv_bfloat16* o = d4 + i * 4;
            o[0] = __float2bfloat16(v.x);
            o[1] = __float2bfloat16(v.y);
            o[2] = __float2bfloat16(v.z);
            o[3] = __float2bfloat16(v.w);
        }
        return;
    }
    const float4* in = (z == 0) ? p0 : (z == 1) ? p1 : (z == 2) ? p2 : p3;
    float*       out = (z == 0) ? d0 : (z == 1) ? d1 : (z == 2) ? d2 : d3;
    if (i < n4w) {
        float4 v = in[i];
        const int base = (i >> 1) * 8 + (i & 1);
        out[base + 0] = to_tf32(v.x);
        out[base + 2] = to_tf32(v.y);
        out[base + 4] = to_tf32(v.z);
        out[base + 6] = to_tf32(v.w);
    }
}
__global__ __launch_bounds__(256)
void conv_x(const float4* __restrict__ p0, const float4* __restrict__ p1,
            const float4* __restrict__ p2,
            float* __restrict__ d0, float* __restrict__ d1,
            float* __restrict__ d2, int n4)
{
    const int z = blockIdx.z;
    const float4* in = (z == 0) ? p0 : (z == 1) ? p1 : p2;
    float*       out = (z == 0) ? d0 : (z == 1) ? d1 : d2;
    int i = blockIdx.x * 256 + threadIdx.x;
    if (i < n4) {
        float4 v = in[i];
        const int base = (i >> 1) * 8 + (i & 1);
        out[base + 0] = to_tf32(v.x);
        out[base + 2] = to_tf32(v.y);
        out[base + 4] = to_tf32(v.z);
        out[base + 6] = to_tf32(v.w);
    }
}

// ---------------------------------------------------------------------------
// QKV projection (R12/13-proven). k-permuted, LDS.64 frags, stride-40.
// ---------------------------------------------------------------------------
__global__ __launch_bounds__(256)
void proj_qkv(const float* __restrict__ bq, const float* __restrict__ bk,
              const float* __restrict__ bv, float* __restrict__ Qout,
              float* __restrict__ Kout)
{
    extern __shared__ float sm[];
    const uint32_t smb = smem_u32(sm);
    constexpr int STG = 2 * 128 * 40;

    const int tid = threadIdx.x, lane = tid & 31, wid = tid >> 5;
    const int g4 = lane >> 2, cq = lane & 3;
    const int wm = (wid & 1) * 64, wn = (wid >> 1) * 32;
    const int z = blockIdx.z;

    const float* Ag = g_Xr[z];
    const float* Bg = (z == 0) ? g_Wq : (z == 1) ? g_Wk : g_Wv;
    const float* bias = (z == 0) ? bq : (z == 1) ? bk : bv;

    const float* Arow = Ag + (size_t)(blockIdx.y * 128) * 1024;
    const float* Brow = Bg + (size_t)(blockIdx.x * 128) * 1024;

    auto loadAB = [&](int t, int s) {
        const uint32_t base = smb + (uint32_t)s * STG * 4;
        const int k0 = t * 32;
#pragma unroll
        for (int i = 0; i < 4; ++i) {
            int idx = tid + i * 256;
            int r = idx >> 3, seg = idx & 7;
            CP_A16(base + (uint32_t)(r * 40 + seg * 4) * 4,
                   Arow + (size_t)r * 1024 + k0 + seg * 4);
        }
#pragma unroll
        for (int i = 0; i < 4; ++i) {
            int idx = tid + i * 256;
            int r = idx >> 3, seg = idx & 7;
            CP_A16(base + (uint32_t)(128 * 40 + r * 40 + seg * 4) * 4,
                   Brow + (size_t)r * 1024 + k0 + seg * 4);
        }
    };

    float acc[4][4][4] = {};

    loadAB(0, 0); CP_COMMIT();

    for (int t = 0; t < 32; ++t) {
        if (t + 1 < 32) { loadAB(t + 1, (t + 1) & 1); CP_COMMIT(); }
        if (t + 1 < 32) { CP_WAIT1(); } else { CP_WAIT0(); }
        __syncthreads();

        const float* As = sm + (t & 1) * STG;
        const float* Bs = As + 128 * 40;
#pragma unroll
        for (int ks = 0; ks < 4; ++ks) {
            uint32_t afr[4][4], bfr[4][2];
#pragma unroll
            for (int m = 0; m < 4; ++m) {
                const float* p = As + (wm + m * 16 + g4) * 40 + ks * 8 + 2 * cq;
                float2 lo = *(const float2*)p;
                float2 hi = *(const float2*)(p + 8 * 40);
                afr[m][0] = __float_as_uint(lo.x);
                afr[m][1] = __float_as_uint(hi.x);
                afr[m][2] = __float_as_uint(lo.y);
                afr[m][3] = __float_as_uint(hi.y);
            }
#pragma unroll
            for (int n = 0; n < 4; ++n) {
                const float* p = Bs + (wn + n * 8 + g4) * 40 + ks * 8 + 2 * cq;
                float2 b = *(const float2*)p;
                bfr[n][0] = __float_as_uint(b.x);
                bfr[n][1] = __float_as_uint(b.y);
            }
#pragma unroll
            for (int m = 0; m < 4; ++m)
#pragma unroll
                for (int n = 0; n < 4; ++n)
                    mma_tf32(acc[m][n], afr[m], bfr[n]);
        }
        __syncthreads();
    }

    float* OUT = (z == 0) ? Qout : Kout;
#pragma unroll
    for (int m = 0; m < 4; ++m) {
#pragma unroll
        for (int n = 0; n < 4; ++n) {
            const int col = wn + n * 8 + cq * 2;
#pragma unroll
            for (int h2 = 0; h2 < 2; ++h2) {
                const int row = wm + m * 16 + g4 + h2 * 8;
                const float c0 = acc[m][n][h2 * 2 + 0];
                const float c1 = acc[m][n][h2 * 2 + 1];
                const int mg = blockIdx.y * 128 + row;
                const int ng = blockIdx.x * 128 + col;
                const int bb = mg / 768, l = mg - bb * 768;
                const int hh = ng >> 6, dd = ng & 63;
                if (z < 2) {
                    float* dst = OUT + (((size_t)(bb * 16 + hh) * 768) + l) * 64 + dd;
                    dst[0] = to_tf32(c0 + bias[ng]);
                    dst[1] = to_tf32(c1 + bias[ng + 1]);
                } else {
                    g_Vt[((size_t)(bb * 16 + hh) * 64 + dd    ) * 768 + l] = to_tf32(c0 + bias[ng]);
                    g_Vt[((size_t)(bb * 16 + hh) * 64 + dd + 1) * 768 + l] = to_tf32(c1 + bias[ng + 1]);
                }
            }
        }
    }
}

// ---------------------------------------------------------------------------
// Output projection (R12/13-proven).
// ---------------------------------------------------------------------------
__global__ __launch_bounds__(256)
void proj_out(const float* __restrict__ bias, float* __restrict__ OUT)
{
    extern __shared__ float sm[];
    const uint32_t smb = smem_u32(sm);
    constexpr int STG = 2 * 128 * 40;

    const int tid = threadIdx.x, lane = tid & 31, wid = tid >> 5;
    const int g4 = lane >> 2, cq = lane & 3;
    const int wm = (wid & 1) * 64, wn = (wid >> 1) * 32;

    const float* Arow = g_O2 + (size_t)(blockIdx.y * 128) * 1024;
    const float* Brow = g_Wo + (size_t)(blockIdx.x * 128) * 1024;

    auto loadAB = [&](int t, int s) {
        const uint32_t base = smb + (uint32_t)s * STG * 4;
        const int k0 = t * 32;
#pragma unroll
        for (int i = 0; i < 4; ++i) {
            int idx = tid + i * 256;
            int r = idx >> 3, seg = idx & 7;
            CP_A16(base + (uint32_t)(r * 40 + seg * 4) * 4,
                   Arow + (size_t)r * 1024 + k0 + seg * 4);
        }
#pragma unroll
        for (int i = 0; i < 4; ++i) {
            int idx = tid + i * 256;
            int r = idx >> 3, seg = idx & 7;
            CP_A16(base + (uint32_t)(128 * 40 + r * 40 + seg * 4) * 4,
                   Brow + (size_t)r * 1024 + k0 + seg * 4);
        }
    };

    float acc[4][4][4] = {};

    loadAB(0, 0); CP_COMMIT();

    for (int t = 0; t < 32; ++t) {
        if (t + 1 < 32) { loadAB(t + 1, (t + 1) & 1); CP_COMMIT(); }
        if (t + 1 < 32) { CP_WAIT1(); } else { CP_WAIT0(); }
        __syncthreads();

        const float* As = sm + (t & 1) * STG;
        const float* Bs = As + 128 * 40;
#pragma unroll
        for (int ks = 0; ks < 4; ++ks) {
            uint32_t afr[4][4], bfr[4][2];
#pragma unroll
            for (int m = 0; m < 4; ++m) {
                const float* p = As + (wm + m * 16 + g4) * 40 + ks * 8 + 2 * cq;
                float2 lo = *(const float2*)p;
                float2 hi = *(const float2*)(p + 8 * 40);
                afr[m][0] = __float_as_uint(lo.x);
                afr[m][1] = __float_as_uint(hi.x);
                afr[m][2] = __float_as_uint(lo.y);
                afr[m][3] = __float_as_uint(hi.y);
            }
#pragma unroll
            for (int n = 0; n < 4; ++n) {
                const float* p = Bs + (wn + n * 8 + g4) * 40 + ks * 8 + 2 * cq;
                float2 b = *(const float2*)p;
                bfr[n][0] = __float_as_uint(b.x);
                bfr[n][1] = __float_as_uint(b.y);
            }
#pragma unroll
            for (int m = 0; m < 4; ++m)
#pragma unroll
                for (int n = 0; n < 4; ++n)
                    mma_tf32(acc[m][n], afr[m], bfr[n]);
        }
        __syncthreads();
    }

#pragma unroll
    for (int m = 0; m < 4; ++m) {
#pragma unroll
        for (int n = 0; n < 4; ++n) {
            const int col = wn + n * 8 + cq * 2;
#pragma unroll
            for (int h2 = 0; h2 < 2; ++h2) {
                const int row = wm + m * 16 + g4 + h2 * 8;
                const int mg = blockIdx.y * 128 + row;
                const int ng = blockIdx.x * 128 + col;
                float* dst = OUT + (size_t)mg * 1024 + ng;
                dst[0] = acc[m][n][h2 * 2 + 0] + bias[ng];
                dst[1] = acc[m][n][h2 * 2 + 1] + bias[ng + 1];
            }
        }
    }
}

// ---------------------------------------------------------------------------
// FULLY FUSED scores + rel + exp + AV. One CTA per (qt, bh).
// Warps: 8 in m (16 q-rows each), full 128 cols per warp.
// Tile stream: w0, w1, c0, w2, c1, ..., w6, c5 (13 tiles).
// Content tile: tf32 S MMA -> +rel(bf16 Wbuf) -> exp -> rowsum ->
//   quad-shuffle p into A-frag layout -> AV MMA with V tile (smem, single
//   slot reloaded per content tile in the same cp.async group as K).
// Epilogue: quad-reduce rowsums, normalize o_acc, write g_O2 (D-permuted).
// smem: Bbuf fp32 2x128x68 | Ebuf bf16 2x128x72 | Wbuf bf16 2x128x136 |
//       Vbuf fp32 64x132.   Q staged fp32 in Wbuf region.
// ---------------------------------------------------------------------------
__global__ __launch_bounds__(256)
void scores_av()
{
    extern __shared__ float sm[];
    constexpr int BB_F = 128 * 68;
    constexpr int E_ELEM = 128 * 72;
    constexpr int W_ELEM = 128 * 136;
    float* Bbuf = sm;
    __nv_bfloat16* Ebuf = (__nv_bfloat16*)(sm + 2 * BB_F);
    __nv_bfloat16* Wbuf = Ebuf + 2 * E_ELEM;
    float* Vbuf = (float*)(Wbuf + 2 * W_ELEM);     // [64][132]
    float* Qstage = (float*)Wbuf;
    const uint32_t bb_a = smem_u32(Bbuf);
    const uint32_t eb_a = smem_u32(Ebuf);
    const uint32_t vb_a = smem_u32(Vbuf);
    const uint32_t wq_a = smem_u32(Qstage);

    const int tid  = threadIdx.x;
    const int lane = tid & 31, wid = tid >> 5;
    const int g4 = lane >> 2, cq = lane & 3;
    const int wm = wid * 16;
    const int qt = blockIdx.x, bh = blockIdx.y;

    const float* Qg = g_Qp + ((size_t)bh * 768 + qt * 128) * 64;
    const float* Kg = g_Kp + (size_t)bh * 768 * 64;
    const float* Vg = g_Vt + (size_t)bh * 64 * 768;
    const int base0 = 640 - qt * 128;

    // stage Q (fp32) into Wbuf region
#pragma unroll
    for (int i = 0; i < 8; ++i) {
        int idx = tid + i * 256;
        int r = idx >> 4, seg = idx & 15;
        CP_A16(wq_a + (uint32_t)(r * 68 + seg * 4) * 4, Qg + r * 64 + seg * 4);
    }
    CP_COMMIT();

    auto loadTile = [&](int i) {
        const bool content = (i >= 2) && ((i & 1) == 0);
        if (content) {
            const int xt = (i - 2) >> 1;
            const uint32_t base = bb_a + (uint32_t)(xt & 1) * (BB_F * 4);
            const float* s0 = Kg + (size_t)xt * 128 * 64;
#pragma unroll
            for (int k = 0; k < 8; ++k) {
                int idx = tid + k * 256;
                int r = idx >> 4, seg = idx & 15;
                CP_A16(base + (uint32_t)(r * 68 + seg * 4) * 4, s0 + r * 64 + seg * 4);
            }
            // V tile xt in the SAME group (single slot; safe: previous AV done)
#pragma unroll
            for (int k = 0; k < 8; ++k) {
                int idx = tid + k * 256;
                int r = idx >> 5, seg = idx & 31;   // 64 rows x 32 segs
                CP_A16(vb_a + (uint32_t)(r * 132 + seg * 4) * 4,
                       Vg + (size_t)r * 768 + xt * 128 + seg * 4);
            }
        } else {
            const int w = (i < 2) ? i : ((i + 1) >> 1);
            const uint32_t base = eb_a + (uint32_t)(w & 1) * (E_ELEM * 2);
            const int jb = base0 + w * 128;
#pragma unroll
            for (int k = 0; k < 4; ++k) {
                int idx = tid + k * 256;
                int r = idx >> 3, seg = idx & 7;
                int j = jb + r;
                int jc = (j > 1534) ? 1534 : j;
                unsigned sz = (j <= 1534) ? 16u : 0u;
                CP_A16Z(base + (uint32_t)(r * 72 + seg * 8) * 2,
                        g_Ec + (size_t)jc * 64 + seg * 8, sz);
            }
        }
    };

    loadTile(0); CP_COMMIT();
    loadTile(1); CP_COMMIT();

    CP_WAIT2();
    __syncthreads();

    // tf32 Q fragments (rows wm+g4, wm+g4+8): [ks8][4]
    uint32_t afr[8][4];
#pragma unroll
    for (int ks = 0; ks < 8; ++ks) {
        const float* q = Qstage + (wm + g4) * 68 + ks * 8 + cq;
        afr[ks][0] = __float_as_uint(q[0]);
        afr[ks][1] = __float_as_uint(q[8 * 68]);
        afr[ks][2] = __float_as_uint(q[4]);
        afr[ks][3] = __float_as_uint(q[8 * 68 + 4]);
    }
    // bf16 Q fragments: [ks16][4]
    uint32_t aqb[4][4];
#pragma unroll
    for (int ks = 0; ks < 4; ++ks) {
        const int row = wm + g4;
        const float* q0 = Qstage + row * 68 + ks * 16;
        const float* q1 = Qstage + (row + 8) * 68 + ks * 16;
        float2 x0 = *(const float2*)(q0 + 2 * cq);
        float2 x1 = *(const float2*)(q0 + 2 * cq + 8);
        float2 y0 = *(const float2*)(q1 + 2 * cq);
        float2 y1 = *(const float2*)(q1 + 2 * cq + 8);
        aqb[ks][0] = pack_bf16(x0.x, x0.y);
        aqb[ks][1] = pack_bf16(y0.x, y0.y);
        aqb[ks][2] = pack_bf16(x1.x, x1.y);
        aqb[ks][3] = pack_bf16(y1.x, y1.y);
    }
    __syncthreads();     // Qstage dead

    CP_WAIT1();
    __syncthreads();

    float o_acc[8][4] = {};          // AV accumulators: 8 d-tiles x 4
    float rs0 = 0.f, rs1 = 0.f;      // row sums (rows wm+g4, wm+g4+8)

    const int srcLo = (lane & ~3) | (cq >> 1);
    const int srcHi = (lane & ~3) | (2 + (cq >> 1));
    const bool oddq = (cq & 1);

#pragma unroll 1
    for (int i = 0; i < 13; ++i) {
        const bool content = (i >= 2) && ((i & 1) == 0);

        if (!content) {
            // ---- window tile: bf16 MMA, 16 n-tiles ----
            const int w = (i < 2) ? i : ((i + 1) >> 1);
            const uint32_t* Eb = (const uint32_t*)(Ebuf + (w & 1) * E_ELEM);
            float acc[16][4] = {};
#pragma unroll
            for (int ks = 0; ks < 4; ++ks) {
#pragma unroll
                for (int nt = 0; nt < 16; ++nt) {
                    const uint32_t* e = Eb + (nt * 8 + g4) * 36 + ks * 8 + cq;
                    uint32_t bfr[2] = { e[0], e[4] };
                    mma_bf16(acc[nt], aqb[ks], bfr);
                }
            }
            __nv_bfloat16* Wd = Wbuf + (w & 1) * W_ELEM;
#pragma unroll
            for (int nt = 0; nt < 16; ++nt) {
                const int col = nt * 8 + 2 * cq;
                *(uint32_t*)((char*)Wd + (size_t)((wm + g4) * 136 + col) * 2) =
                    pack_bf16(acc[nt][0], acc[nt][1]);
                *(uint32_t*)((char*)Wd + (size_t)((wm + g4 + 8) * 136 + col) * 2) =
                    pack_bf16(acc[nt][2], acc[nt][3]);
            }
        } else {
            // ---- content tile: tf32 S MMA, then rel+exp+AV ----
            const int xt = (i - 2) >> 1;
            const float* Bsb = Bbuf + (xt & 1) * BB_F;
            float acc[16][4] = {};
#pragma unroll
            for (int ks = 0; ks < 8; ++ks) {
#pragma unroll
                for (int nt = 0; nt < 16; ++nt) {
                    const float* b = Bsb + (nt * 8 + g4) * 68 + ks * 8 + cq;
                    uint32_t bfr[2] = { __float_as_uint(b[0]), __float_as_uint(b[4]) };
                    mma_tf32(acc[nt], afr[ks], bfr);
                }
            }
            // rel + exp (in C-frag layout), rowsums
            const __nv_bfloat16* W0 = Wbuf + (xt & 1) * W_ELEM;
            const __nv_bfloat16* W1 = Wbuf + ((xt + 1) & 1) * W_ELEM;
            const int r0i = wm + g4, r1i = wm + g4 + 8;
#pragma unroll
            for (int nt = 0; nt < 16; ++nt) {
                const int col = nt * 8 + 2 * cq;
                int c0 = col - r0i + 127, c1 = c0 + 1;
                float e0 = __bfloat162float((c0 < 128) ? W0[r0i * 136 + c0]
                                                       : W1[r0i * 136 + c0 - 128]);
                float e1 = __bfloat162float((c1 < 128) ? W0[r0i * 136 + c1]
                                                       : W1[r0i * 136 + c1 - 128]);
                int d0 = col - r1i + 127, d1 = d0 + 1;
                float f0 = __bfloat162float((d0 < 128) ? W0[r1i * 136 + d0]
                                                       : W1[r1i * 136 + d0 - 128]);
                float f1 = __bfloat162float((d1 < 128) ? W0[r1i * 136 + d1]
                                                       : W1[r1i * 136 + d1 - 128]);
                float p0 = __expf(SCALE * (acc[nt][0] + e0));
                float p1 = __expf(SCALE * (acc[nt][1] + e1));
                float p2 = __expf(SCALE * (acc[nt][2] + f0));
                float p3 = __expf(SCALE * (acc[nt][3] + f1));
                rs0 += p0 + p1;
                rs1 += p2 + p3;
                acc[nt][0] = to_tf32(p0);
                acc[nt][1] = to_tf32(p1);
                acc[nt][2] = to_tf32(p2);
                acc[nt][3] = to_tf32(p3);
            }
            // AV: per k-group, shuffle p C-frag -> A-frag, MMA with V
#pragma unroll
            for (int kk = 0; kk < 16; ++kk) {
                float x0 = __shfl_sync(0xffffffffu, acc[kk][0], srcLo);
                float x1 = __shfl_sync(0xffffffffu, acc[kk][1], srcLo);
                float y0 = __shfl_sync(0xffffffffu, acc[kk][0], srcHi);
                float y1 = __shfl_sync(0xffffffffu, acc[kk][1], srcHi);
                float z0 = __shfl_sync(0xffffffffu, acc[kk][2], srcLo);
                float z1 = __shfl_sync(0xffffffffu, acc[kk][3], srcLo);
                float u0 = __shfl_sync(0xffffffffu, acc[kk][2], srcHi);
                float u1 = __shfl_sync(0xffffffffu, acc[kk][3], srcHi);
                uint32_t a[4];
                a[0] = __float_as_uint(oddq ? x1 : x0);   // P[g4][cq]
                a[1] = __float_as_uint(oddq ? z1 : z0);   // P[g4+8][cq]
                a[2] = __float_as_uint(oddq ? y1 : y0);   // P[g4][cq+4]
                a[3] = __float_as_uint(oddq ? u1 : u0);   // P[g4+8][cq+4]
#pragma unroll
                for (int dt = 0; dt < 8; ++dt) {
                    const float* v = Vbuf + (dt * 8 + g4) * 132 + kk * 8 + cq;
                    uint32_t bfr[2] = { __float_as_uint(v[0]), __float_as_uint(v[4]) };
                    mma_tf32(o_acc[dt], a, bfr);
                }
            }
        }

        __syncthreads();
        if (i + 2 < 13) { loadTile(i + 2); CP_COMMIT(); }
        if (i + 1 < 13) {
            if (i + 2 < 13) { CP_WAIT1(); } else { CP_WAIT0(); }
            __syncthreads();
        }
    }

    // full row sums via quad reduce (warp owns its rows exclusively)
    rs0 += __shfl_xor_sync(0xffffffffu, rs0, 1);
    rs0 += __shfl_xor_sync(0xffffffffu, rs0, 2);
    rs1 += __shfl_xor_sync(0xffffffffu, rs1, 1);
    rs1 += __shfl_xor_sync(0xffffffffu, rs1, 2);
    const float inv0 = 1.0f / rs0, inv1 = 1.0f / rs1;

    const int b = bh >> 4, h = bh & 15;
    const int j0 = 2 * cq;
    const int pp0 = (j0 & 3) * 2 + (j0 >> 2);
    const int pp1 = ((j0 + 1) & 3) * 2 + ((j0 + 1) >> 2);
    const int q0r = qt * 128 + wm + g4;
    const int q1r = q0r + 8;
#pragma unroll
    for (int dt = 0; dt < 8; ++dt) {
        float* dst0 = g_O2 + ((size_t)(b * 768) + q0r) * 1024 + h * 64 + dt * 8;
        float* dst1 = g_O2 + ((size_t)(b * 768) + q1r) * 1024 + h * 64 + dt * 8;
        dst0[pp0] = to_tf32(o_acc[dt][0] * inv0);
        dst0[pp1] = to_tf32(o_acc[dt][1] * inv0);
        dst1[pp0] = to_tf32(o_acc[dt][2] * inv1);
        dst1[pp1] = to_tf32(o_acc[dt][3] * inv1);
    }
}

// ---------------------------------------------------------------------------
extern "C" void kernel_launch(void* const* d_in, const int* in_sizes, int n_in,
                              void* d_out, int out_size)
{
    const float* query = (const float*)d_in[0];
    const float* key   = (const float*)d_in[1];
    const float* value = (const float*)d_in[2];
    const float* w_q   = (const float*)d_in[3];
    const float* b_q   = (const float*)d_in[4];
    const float* w_k   = (const float*)d_in[5];
    const float* b_k   = (const float*)d_in[6];
    const float* w_v   = (const float*)d_in[7];
    const float* b_v   = (const float*)d_in[8];
    const float* w_o   = (const float*)d_in[9];
    const float* b_o   = (const float*)d_in[10];
    const float* relE  = (const float*)d_in[11];
    float* out = (float*)d_out;

    float *xr, *wq, *wk, *wv, *wo, *qp, *kp;
    __nv_bfloat16* ec;
    cudaGetSymbolAddress((void**)&xr, g_Xr);
    cudaGetSymbolAddress((void**)&wq, g_Wq);
    cudaGetSymbolAddress((void**)&wk, g_Wk);
    cudaGetSymbolAddress((void**)&wv, g_Wv);
    cudaGetSymbolAddress((void**)&wo, g_Wo);
    cudaGetSymbolAddress((void**)&qp, g_Qp);
    cudaGetSymbolAddress((void**)&kp, g_Kp);
    cudaGetSymbolAddress((void**)&ec, g_Ec);

    const int SMEMP   = 2 * 2 * 128 * 40 * 4;                    // 81920
    const int SC_SMEM = 2 * 128 * 68 * 4 + 2 * 128 * 72 * 2
                      + 2 * 128 * 136 * 2 + 64 * 132 * 4;        // 209920
    cudaFuncSetAttribute(proj_qkv,  cudaFuncAttributeMaxDynamicSharedMemorySize, SMEMP);
    cudaFuncSetAttribute(proj_out,  cudaFuncAttributeMaxDynamicSharedMemorySize, SMEMP);
    cudaFuncSetAttribute(scores_av, cudaFuncAttributeMaxDynamicSharedMemorySize, SC_SMEM);

    const int NW4 = 1024 * 1024 / 4;
    const int NE4 = 1535 * 64 / 4;
    const int NX4 = M_ * D_ / 4;

    conv_w<<<dim3((NW4 + 255) / 256, 1, 5), 256>>>(
        (const float4*)w_q, (const float4*)w_k, (const float4*)w_v,
        (const float4*)w_o, (const float4*)relE,
        wq, wk, wv, wo, ec, NW4, NE4);

    conv_x<<<dim3((NX4 + 255) / 256, 1, 3), 256>>>(
        (const float4*)query, (const float4*)key, (const float4*)value,
        xr, xr + M_ * D_, xr + 2 * M_ * D_, NX4);

    proj_qkv<<<dim3(8, 48, 3), 256, SMEMP>>>(b_q, b_k, b_v, qp, kp);

    scores_av<<<dim3(6, 128), 256, SC_SMEM>>>();

    proj_out<<<dim3(8, 48), 256, SMEMP>>>(b_o, out);
}